// round 3
// baseline (speedup 1.0000x reference)
#include <cuda_runtime.h>

#define BB 256
#define TT 256
#define CC 384
#define HS 64
#define BT (BB*TT)

// Scratch (allocation-free rule: __device__ globals)
__device__ float g_q[BT*HS];
__device__ float g_k[BT*HS];
__device__ float g_v[BT*HS];

// ---------------------------------------------------------------------------
// QKV projection: out[BT,192] = x[BT,384] @ [Wq|Wk|Wv] + bias
// CTA tile: 64 rows x 192 cols, K-tile 16. Thread tile 4x12 (256 thr = 16x16).
// ---------------------------------------------------------------------------
__global__ __launch_bounds__(256) void qkv_kernel(
    const float* __restrict__ x,
    const float* __restrict__ Wq, const float* __restrict__ bq,
    const float* __restrict__ Wk, const float* __restrict__ bk,
    const float* __restrict__ Wv, const float* __restrict__ bv)
{
    __shared__ float xs[64][20];   // [row][k], pad 20 keeps float4 stores aligned
    __shared__ float ws[16][192];  // [k][col]

    const int tid = threadIdx.x;
    const int tr  = tid >> 4;   // 0..15 (row group)
    const int tc  = tid & 15;   // 0..15 (col group)
    const int rowbase = blockIdx.x * 64;

    float acc[4][12];
    #pragma unroll
    for (int i = 0; i < 4; i++)
        #pragma unroll
        for (int j = 0; j < 12; j++) acc[i][j] = 0.f;

    const int xr = tid >> 2;         // 0..63
    const int xk = (tid & 3) << 2;   // 0,4,8,12

    for (int k0 = 0; k0 < CC; k0 += 16) {
        // stage x tile: 64x16
        float4 xv = *(const float4*)(x + (size_t)(rowbase + xr) * CC + k0 + xk);
        *(float4*)&xs[xr][xk] = xv;
        // stage W tile: 16x192 (three matrices side by side)
        #pragma unroll
        for (int p = 0; p < 3; p++) {
            int e4 = tid + 256 * p;        // 0..767
            int kk = e4 / 48;              // 0..15
            int cq = (e4 % 48) << 2;       // 0..188 step 4
            const float* W = (cq < 64) ? Wq : (cq < 128 ? Wk : Wv);
            int cc2 = cq & 63;
            *(float4*)&ws[kk][cq] = *(const float4*)(W + (size_t)(k0 + kk) * HS + cc2);
        }
        __syncthreads();

        #pragma unroll
        for (int kk = 0; kk < 16; kk++) {
            float a[4], bb[12];
            #pragma unroll
            for (int i = 0; i < 4; i++) a[i] = xs[tr + 16 * i][kk];
            #pragma unroll
            for (int j = 0; j < 12; j++) bb[j] = ws[kk][tc + 16 * j];
            #pragma unroll
            for (int i = 0; i < 4; i++)
                #pragma unroll
                for (int j = 0; j < 12; j++)
                    acc[i][j] = fmaf(a[i], bb[j], acc[i][j]);
        }
        __syncthreads();
    }

    // epilogue: add bias, scatter to q/k/v scratch
    #pragma unroll
    for (int i = 0; i < 4; i++) {
        int r = rowbase + tr + 16 * i;
        #pragma unroll
        for (int j = 0; j < 12; j++) {
            int c = tc + 16 * j;
            float val = acc[i][j];
            if (j < 4)        g_q[(size_t)r * HS + c]         = val + bq[c];
            else if (j < 8)   g_k[(size_t)r * HS + (c - 64)]  = val + bk[c - 64];
            else              g_v[(size_t)r * HS + (c - 128)] = val + bv[c - 128];
        }
    }
}

// ---------------------------------------------------------------------------
// Attention: one CTA per batch. K,V resident in smem (131 KB fp32).
// One thread per query row, online softmax, float4 broadcast smem reads.
// ---------------------------------------------------------------------------
__global__ __launch_bounds__(256) void attn_kernel(float* __restrict__ out)
{
    extern __shared__ float sm[];
    float* Ks = sm;                  // [T][HS]
    float* Vs = sm + TT * HS;        // [T][HS]

    const int b = blockIdx.x;
    const int t = threadIdx.x;

    const float4* kg = (const float4*)(g_k + (size_t)b * TT * HS);
    const float4* vg = (const float4*)(g_v + (size_t)b * TT * HS);
    for (int e = t; e < TT * HS / 4; e += 256) {
        ((float4*)Ks)[e] = kg[e];
        ((float4*)Vs)[e] = vg[e];
    }
    __syncthreads();

    float q[HS];
    const float* qg = g_q + ((size_t)b * TT + t) * HS;
    #pragma unroll
    for (int d = 0; d < HS; d++) q[d] = qg[d] * 0.125f;   // scale = HS^-0.5 = 1/8

    float m = -1e30f, l = 0.f;
    float acc[HS];
    #pragma unroll
    for (int d = 0; d < HS; d++) acc[d] = 0.f;

    for (int s = 0; s <= t; s++) {
        const float4* kp = (const float4*)(Ks + s * HS);
        float dA = 0.f, dB = 0.f, dC = 0.f, dD = 0.f;
        #pragma unroll
        for (int u = 0; u < 16; u++) {
            float4 kv = kp[u];
            dA = fmaf(q[4 * u + 0], kv.x, dA);
            dB = fmaf(q[4 * u + 1], kv.y, dB);
            dC = fmaf(q[4 * u + 2], kv.z, dC);
            dD = fmaf(q[4 * u + 3], kv.w, dD);
        }
        float dot = (dA + dB) + (dC + dD);

        float nm   = fmaxf(m, dot);
        float p    = __expf(dot - nm);
        float corr = __expf(m - nm);
        l = l * corr + p;

        const float4* vp = (const float4*)(Vs + s * HS);
        #pragma unroll
        for (int u = 0; u < 16; u++) {
            float4 vv = vp[u];
            acc[4 * u + 0] = fmaf(p, vv.x, acc[4 * u + 0] * corr);
            acc[4 * u + 1] = fmaf(p, vv.y, acc[4 * u + 1] * corr);
            acc[4 * u + 2] = fmaf(p, vv.z, acc[4 * u + 2] * corr);
            acc[4 * u + 3] = fmaf(p, vv.w, acc[4 * u + 3] * corr);
        }
        m = nm;
    }

    float inv = 1.f / l;
    float* op = out + ((size_t)b * TT + t) * HS;
    #pragma unroll
    for (int d = 0; d < HS; d++) op[d] = acc[d] * inv;
}

extern "C" void kernel_launch(void* const* d_in, const int* in_sizes, int n_in,
                              void* d_out, int out_size)
{
    const float* x  = (const float*)d_in[0];
    const float* Wq = (const float*)d_in[1];
    const float* bq = (const float*)d_in[2];
    const float* Wk = (const float*)d_in[3];
    const float* bk = (const float*)d_in[4];
    const float* Wv = (const float*)d_in[5];
    const float* bv = (const float*)d_in[6];
    float* out = (float*)d_out;

    qkv_kernel<<<BT / 64, 256>>>(x, Wq, bq, Wk, bk, Wv, bv);

    const int smem_bytes = 2 * TT * HS * (int)sizeof(float);  // 131072
    cudaFuncSetAttribute(attn_kernel, cudaFuncAttributeMaxDynamicSharedMemorySize, smem_bytes);
    attn_kernel<<<BB, 256, smem_bytes>>>(out);
}

// round 5
// speedup vs baseline: 2.7702x; 2.7702x over previous
#include <cuda_runtime.h>

#define BB 256
#define TT 256
#define CC 384
#define HS 64
#define BT (BB*TT)

typedef unsigned int u32;

// Scratch (allocation-free rule: __device__ globals)
__device__ float g_q[BT*HS];
__device__ float g_k[BT*HS];
__device__ float g_v[BT*HS];

// ---------------------------------------------------------------------------
// tf32 helpers
// ---------------------------------------------------------------------------
__device__ __forceinline__ u32 f2tf(float f) {
    u32 u;
    asm("cvt.rna.tf32.f32 %0, %1;" : "=r"(u) : "f"(f));
    return u;
}

__device__ __forceinline__ void mma_tf32(float c[4], const u32 a[4], u32 b0, u32 b1) {
    asm volatile(
        "mma.sync.aligned.m16n8k8.row.col.f32.tf32.tf32.f32 "
        "{%0,%1,%2,%3}, {%4,%5,%6,%7}, {%8,%9}, {%0,%1,%2,%3};\n"
        : "+f"(c[0]), "+f"(c[1]), "+f"(c[2]), "+f"(c[3])
        : "r"(a[0]), "r"(a[1]), "r"(a[2]), "r"(a[3]), "r"(b0), "r"(b1));
}

// ---------------------------------------------------------------------------
// QKV projection with tf32 tensor-core MMA.
// out[BT,64] = x[BT,384] @ W[384,64] + b   for W in {Wq,Wk,Wv} (blockIdx.y)
// CTA tile 128x64, K-tile 32. 8 warps: 4(m) x 2(n), warp tile 32x32.
// ---------------------------------------------------------------------------
#define XS_STRIDE 36
#define WS_STRIDE 68

__global__ __launch_bounds__(256) void qkv_tc_kernel(
    const float* __restrict__ x,
    const float* __restrict__ Wq, const float* __restrict__ bq,
    const float* __restrict__ Wk, const float* __restrict__ bk,
    const float* __restrict__ Wv, const float* __restrict__ bv)
{
    __shared__ u32 Xs[128 * XS_STRIDE];   // 128 rows x 32 k (tf32 bits), stride 36
    __shared__ u32 Ws[32 * WS_STRIDE];    // 32 k x 64 cols (tf32 bits), stride 68

    const int tid  = threadIdx.x;
    const int wid  = tid >> 5;
    const int lane = tid & 31;
    const int gid  = lane >> 2;   // 0..7
    const int tig  = lane & 3;    // 0..3
    const int wm   = wid >> 1;    // 0..3  (row group * 32)
    const int wn   = wid & 1;     // 0..1  (col group * 32)
    const int rowbase = blockIdx.x * 128;
    const int by = blockIdx.y;

    const float* W    = (by == 0) ? Wq : (by == 1) ? Wk : Wv;
    const float* bias = (by == 0) ? bq : (by == 1) ? bk : bv;
    float* outp       = (by == 0) ? g_q : (by == 1) ? g_k : g_v;

    float acc[2][4][4];
    #pragma unroll
    for (int i = 0; i < 2; i++)
        #pragma unroll
        for (int j = 0; j < 4; j++)
            #pragma unroll
            for (int r = 0; r < 4; r++) acc[i][j][r] = 0.f;

    for (int k0 = 0; k0 < CC; k0 += 32) {
        // stage x tile 128x32 -> Xs (tf32)
        #pragma unroll
        for (int i = 0; i < 4; i++) {
            int e   = tid + 256 * i;         // 0..1023 float4s
            int row = e >> 3;
            int c4  = (e & 7) << 2;
            float4 v = *(const float4*)(x + (size_t)(rowbase + row) * CC + k0 + c4);
            u32* d = &Xs[row * XS_STRIDE + c4];
            d[0] = f2tf(v.x); d[1] = f2tf(v.y); d[2] = f2tf(v.z); d[3] = f2tf(v.w);
        }
        // stage W tile 32x64 -> Ws (tf32)
        #pragma unroll
        for (int i = 0; i < 2; i++) {
            int e   = tid + 256 * i;         // 0..511 float4s
            int row = e >> 4;
            int c4  = (e & 15) << 2;
            float4 v = *(const float4*)(W + (size_t)(k0 + row) * HS + c4);
            u32* d = &Ws[row * WS_STRIDE + c4];
            d[0] = f2tf(v.x); d[1] = f2tf(v.y); d[2] = f2tf(v.z); d[3] = f2tf(v.w);
        }
        __syncthreads();

        #pragma unroll
        for (int ks = 0; ks < 4; ks++) {
            u32 a[2][4];
            #pragma unroll
            for (int mt = 0; mt < 2; mt++) {
                int rb = wm * 32 + mt * 16;
                a[mt][0] = Xs[(rb + gid)     * XS_STRIDE + ks * 8 + tig];
                a[mt][1] = Xs[(rb + gid + 8) * XS_STRIDE + ks * 8 + tig];
                a[mt][2] = Xs[(rb + gid)     * XS_STRIDE + ks * 8 + tig + 4];
                a[mt][3] = Xs[(rb + gid + 8) * XS_STRIDE + ks * 8 + tig + 4];
            }
            u32 b[4][2];
            #pragma unroll
            for (int nt = 0; nt < 4; nt++) {
                int col = wn * 32 + nt * 8 + gid;
                b[nt][0] = Ws[(ks * 8 + tig)     * WS_STRIDE + col];
                b[nt][1] = Ws[(ks * 8 + tig + 4) * WS_STRIDE + col];
            }
            #pragma unroll
            for (int mt = 0; mt < 2; mt++)
                #pragma unroll
                for (int nt = 0; nt < 4; nt++)
                    mma_tf32(acc[mt][nt], a[mt], b[nt][0], b[nt][1]);
        }
        __syncthreads();
    }

    // epilogue: bias + store fp32
    #pragma unroll
    for (int nt = 0; nt < 4; nt++) {
        int col = wn * 32 + nt * 8 + 2 * tig;
        float b0 = bias[col], b1 = bias[col + 1];
        #pragma unroll
        for (int mt = 0; mt < 2; mt++) {
            int r0 = rowbase + wm * 32 + mt * 16 + gid;
            float2 v0 = make_float2(acc[mt][nt][0] + b0, acc[mt][nt][1] + b1);
            float2 v1 = make_float2(acc[mt][nt][2] + b0, acc[mt][nt][3] + b1);
            *(float2*)(outp + (size_t)r0 * HS + col)       = v0;
            *(float2*)(outp + (size_t)(r0 + 8) * HS + col) = v1;
        }
    }
}

// ---------------------------------------------------------------------------
// Flash attention with tf32 tensor-core MMA.
// Grid: (2 query blocks of 128, 256 batches). 8 warps x 16 query rows each.
// Key/value blocks of 64 staged in smem as tf32. P routed via per-warp smem.
// ---------------------------------------------------------------------------
#define KS_STRIDE 68
#define VS_STRIDE 72
#define PS_STRIDE 68   // P tile is 16x64 (K=64) -> stride must cover 64 cols
#define QS_STRIDE 68

__global__ __launch_bounds__(256) void attn_tc_kernel(float* __restrict__ out)
{
    extern __shared__ u32 sm[];
    u32* Ks = sm;                              // [64][68]
    u32* Vs = sm + 64 * KS_STRIDE;             // [64][72]
    u32* Ps = sm + 64 * KS_STRIDE + 64 * VS_STRIDE;  // [8][16][68]
    u32* Qs = sm;                              // staging [128][68] (overlaps Ks+Vs)

    const int tid  = threadIdx.x;
    const int wid  = tid >> 5;
    const int lane = tid & 31;
    const int gid  = lane >> 2;
    const int tig  = lane & 3;
    const int b  = blockIdx.y;
    const int qb = blockIdx.x;

    // ---- stage Q (scaled, tf32) and load fragments ----
    const float4* qg = (const float4*)(g_q + ((size_t)(b * TT) + qb * 128) * HS);
    #pragma unroll
    for (int i = 0; i < 8; i++) {
        int e   = tid + 256 * i;       // 0..2047 float4s
        int row = e >> 4;
        int c4  = (e & 15) << 2;
        float4 v = qg[e];
        u32* d = &Qs[row * QS_STRIDE + c4];
        d[0] = f2tf(v.x * 0.125f); d[1] = f2tf(v.y * 0.125f);
        d[2] = f2tf(v.z * 0.125f); d[3] = f2tf(v.w * 0.125f);
    }
    __syncthreads();

    u32 qf[8][4];
    {
        int rb = wid * 16;
        #pragma unroll
        for (int k = 0; k < 8; k++) {
            qf[k][0] = Qs[(rb + gid)     * QS_STRIDE + k * 8 + tig];
            qf[k][1] = Qs[(rb + gid + 8) * QS_STRIDE + k * 8 + tig];
            qf[k][2] = Qs[(rb + gid)     * QS_STRIDE + k * 8 + tig + 4];
            qf[k][3] = Qs[(rb + gid + 8) * QS_STRIDE + k * 8 + tig + 4];
        }
    }
    __syncthreads();   // done with Q staging region

    float o[8][4];
    #pragma unroll
    for (int j = 0; j < 8; j++)
        #pragma unroll
        for (int r = 0; r < 4; r++) o[j][r] = 0.f;

    float m0 = -1e30f, m1 = -1e30f, l0 = 0.f, l1 = 0.f;
    const int row0 = qb * 128 + wid * 16 + gid;   // rows for c0,c1
    const int row1 = row0 + 8;                    // rows for c2,c3
    const int wrow_max = qb * 128 + wid * 16 + 15;

    const int nkb = 2 * qb + 2;   // causal: key blocks 0 .. 2*qb+1
    for (int kb = 0; kb < nkb; kb++) {
        const int kbase = kb * 64;
        // ---- stage K/V block (tf32) ----
        const float4* kg4 = (const float4*)(g_k + ((size_t)(b * TT) + kbase) * HS);
        const float4* vg4 = (const float4*)(g_v + ((size_t)(b * TT) + kbase) * HS);
        #pragma unroll
        for (int i = 0; i < 4; i++) {
            int e   = tid + 256 * i;    // 0..1023 float4s
            int row = e >> 4;
            int c4  = (e & 15) << 2;
            float4 kv = kg4[e];
            u32* dk = &Ks[row * KS_STRIDE + c4];
            dk[0] = f2tf(kv.x); dk[1] = f2tf(kv.y); dk[2] = f2tf(kv.z); dk[3] = f2tf(kv.w);
            float4 vv = vg4[e];
            u32* dv = &Vs[row * VS_STRIDE + c4];
            dv[0] = f2tf(vv.x); dv[1] = f2tf(vv.y); dv[2] = f2tf(vv.z); dv[3] = f2tf(vv.w);
        }
        __syncthreads();

        if (kbase <= wrow_max) {      // warp-uniform: skip fully-masked blocks
            // ---- S = Q K^T over this block (16 x 64 per warp) ----
            float s[8][4];
            #pragma unroll
            for (int j = 0; j < 8; j++) {
                s[j][0] = s[j][1] = s[j][2] = s[j][3] = 0.f;
                #pragma unroll
                for (int k = 0; k < 8; k++) {
                    u32 b0 = Ks[(j * 8 + gid) * KS_STRIDE + k * 8 + tig];
                    u32 b1 = Ks[(j * 8 + gid) * KS_STRIDE + k * 8 + tig + 4];
                    mma_tf32(s[j], qf[k], b0, b1);
                }
            }
            // ---- causal mask ----
            if (kbase + 63 > row0) {
                #pragma unroll
                for (int j = 0; j < 8; j++) {
                    int key0 = kbase + j * 8 + 2 * tig;
                    int key1 = key0 + 1;
                    if (key0 > row0) s[j][0] = -1e30f;
                    if (key1 > row0) s[j][1] = -1e30f;
                    if (key0 > row1) s[j][2] = -1e30f;
                    if (key1 > row1) s[j][3] = -1e30f;
                }
            }
            // ---- online softmax ----
            float mx0 = -1e30f, mx1 = -1e30f;
            #pragma unroll
            for (int j = 0; j < 8; j++) {
                mx0 = fmaxf(mx0, fmaxf(s[j][0], s[j][1]));
                mx1 = fmaxf(mx1, fmaxf(s[j][2], s[j][3]));
            }
            mx0 = fmaxf(mx0, __shfl_xor_sync(0xffffffffu, mx0, 1));
            mx0 = fmaxf(mx0, __shfl_xor_sync(0xffffffffu, mx0, 2));
            mx1 = fmaxf(mx1, __shfl_xor_sync(0xffffffffu, mx1, 1));
            mx1 = fmaxf(mx1, __shfl_xor_sync(0xffffffffu, mx1, 2));

            float nm0 = fmaxf(m0, mx0), nm1 = fmaxf(m1, mx1);
            float cr0 = __expf(m0 - nm0), cr1 = __expf(m1 - nm1);
            m0 = nm0; m1 = nm1;

            u32* Pw = Ps + wid * 16 * PS_STRIDE;
            float sum0 = 0.f, sum1 = 0.f;
            #pragma unroll
            for (int j = 0; j < 8; j++) {
                float p0 = __expf(s[j][0] - nm0);
                float p1 = __expf(s[j][1] - nm0);
                float p2 = __expf(s[j][2] - nm1);
                float p3 = __expf(s[j][3] - nm1);
                sum0 += p0 + p1; sum1 += p2 + p3;
                int co = j * 8 + 2 * tig;
                Pw[gid * PS_STRIDE + co]           = f2tf(p0);
                Pw[gid * PS_STRIDE + co + 1]       = f2tf(p1);
                Pw[(gid + 8) * PS_STRIDE + co]     = f2tf(p2);
                Pw[(gid + 8) * PS_STRIDE + co + 1] = f2tf(p3);
            }
            sum0 += __shfl_xor_sync(0xffffffffu, sum0, 1);
            sum0 += __shfl_xor_sync(0xffffffffu, sum0, 2);
            sum1 += __shfl_xor_sync(0xffffffffu, sum1, 1);
            sum1 += __shfl_xor_sync(0xffffffffu, sum1, 2);
            l0 = l0 * cr0 + sum0;
            l1 = l1 * cr1 + sum1;

            // rescale O
            #pragma unroll
            for (int j = 0; j < 8; j++) {
                o[j][0] *= cr0; o[j][1] *= cr0;
                o[j][2] *= cr1; o[j][3] *= cr1;
            }
            __syncwarp();

            // ---- O += P V ----
            #pragma unroll
            for (int kt = 0; kt < 8; kt++) {
                u32 a[4];
                a[0] = Pw[gid * PS_STRIDE + kt * 8 + tig];
                a[1] = Pw[(gid + 8) * PS_STRIDE + kt * 8 + tig];
                a[2] = Pw[gid * PS_STRIDE + kt * 8 + tig + 4];
                a[3] = Pw[(gid + 8) * PS_STRIDE + kt * 8 + tig + 4];
                #pragma unroll
                for (int j = 0; j < 8; j++) {
                    u32 b0 = Vs[(kt * 8 + tig)     * VS_STRIDE + j * 8 + gid];
                    u32 b1 = Vs[(kt * 8 + tig + 4) * VS_STRIDE + j * 8 + gid];
                    mma_tf32(o[j], a, b0, b1);
                }
            }
        }
        __syncthreads();
    }

    // ---- epilogue ----
    float inv0 = 1.f / l0, inv1 = 1.f / l1;
    #pragma unroll
    for (int j = 0; j < 8; j++) {
        int col = j * 8 + 2 * tig;
        float2 v0 = make_float2(o[j][0] * inv0, o[j][1] * inv0);
        float2 v1 = make_float2(o[j][2] * inv1, o[j][3] * inv1);
        *(float2*)(out + ((size_t)b * TT + row0) * HS + col) = v0;
        *(float2*)(out + ((size_t)b * TT + row1) * HS + col) = v1;
    }
}

extern "C" void kernel_launch(void* const* d_in, const int* in_sizes, int n_in,
                              void* d_out, int out_size)
{
    const float* x  = (const float*)d_in[0];
    const float* Wq = (const float*)d_in[1];
    const float* bq = (const float*)d_in[2];
    const float* Wk = (const float*)d_in[3];
    const float* bk = (const float*)d_in[4];
    const float* Wv = (const float*)d_in[5];
    const float* bv = (const float*)d_in[6];
    float* out = (float*)d_out;

    dim3 qkv_grid(BT / 128, 3);
    qkv_tc_kernel<<<qkv_grid, 256>>>(x, Wq, bq, Wk, bk, Wv, bv);

    const int smem_bytes = (64 * KS_STRIDE + 64 * VS_STRIDE + 8 * 16 * PS_STRIDE) * 4;
    cudaFuncSetAttribute(attn_tc_kernel, cudaFuncAttributeMaxDynamicSharedMemorySize, smem_bytes);
    dim3 attn_grid(2, BB);
    attn_tc_kernel<<<attn_grid, 256, smem_bytes>>>(out);
}

// round 6
// speedup vs baseline: 3.7929x; 1.3692x over previous
#include <cuda_runtime.h>

#define BB 256
#define TT 256
#define CC 384
#define HS 64
#define BT (BB*TT)

typedef unsigned int u32;

// Scratch (allocation-free rule: __device__ globals)
__device__ float g_q[BT*HS];
__device__ float g_k[BT*HS];
__device__ float g_v[BT*HS];

// ---------------------------------------------------------------------------
// tf32 helpers
// ---------------------------------------------------------------------------
__device__ __forceinline__ u32 f2tf(float f) {
    u32 u;
    asm("cvt.rna.tf32.f32 %0, %1;" : "=r"(u) : "f"(f));
    return u;
}

__device__ __forceinline__ void mma_tf32(float c[4], const u32 a[4], u32 b0, u32 b1) {
    asm volatile(
        "mma.sync.aligned.m16n8k8.row.col.f32.tf32.tf32.f32 "
        "{%0,%1,%2,%3}, {%4,%5,%6,%7}, {%8,%9}, {%0,%1,%2,%3};\n"
        : "+f"(c[0]), "+f"(c[1]), "+f"(c[2]), "+f"(c[3])
        : "r"(a[0]), "r"(a[1]), "r"(a[2]), "r"(a[3]), "r"(b0), "r"(b1));
}

// ---------------------------------------------------------------------------
// Fused QKV projection with tf32 tensor-core MMA. x is read ONCE.
// out[BT,192] = x[BT,384] @ [Wq|Wk|Wv] + [bq|bk|bv]
// CTA tile 128x192, K-tile 32. 8 warps: 4(m) x 2(n), warp tile 32x96.
// Register-prefetch pipeline: next tile LDGs issue before the MMA block.
// ---------------------------------------------------------------------------
#define XS_STRIDE 36
#define WS_STRIDE 200   // == 8 (mod 32): B-frag LDS conflict-free

__global__ __launch_bounds__(256) void qkv_tc_kernel(
    const float* __restrict__ x,
    const float* __restrict__ Wq, const float* __restrict__ bq,
    const float* __restrict__ Wk, const float* __restrict__ bk,
    const float* __restrict__ Wv, const float* __restrict__ bv)
{
    __shared__ u32 Xs[128 * XS_STRIDE];   // 128 rows x 32 k (tf32 bits)
    __shared__ u32 Ws[32 * WS_STRIDE];    // 32 k x 192 cols (tf32 bits)

    const int tid  = threadIdx.x;
    const int wid  = tid >> 5;
    const int lane = tid & 31;
    const int gid  = lane >> 2;   // 0..7
    const int tig  = lane & 3;    // 0..3
    const int wm   = wid >> 1;    // 0..3  (row group * 32)
    const int wn   = wid & 1;     // 0..1  (col group * 96)
    const int rowbase = blockIdx.x * 128;

    float acc[2][12][4];
    #pragma unroll
    for (int i = 0; i < 2; i++)
        #pragma unroll
        for (int j = 0; j < 12; j++)
            #pragma unroll
            for (int r = 0; r < 4; r++) acc[i][j][r] = 0.f;

    float4 xr[4];   // staged x:  4 float4 / thread (128x32)
    float4 wr[6];   // staged W:  6 float4 / thread (32x192)

    // prologue: load first tile
    #pragma unroll
    for (int i = 0; i < 4; i++) {
        int e   = tid + 256 * i;
        int row = e >> 3;
        int c4  = (e & 7) << 2;
        xr[i] = *(const float4*)(x + (size_t)(rowbase + row) * CC + c4);
    }
    #pragma unroll
    for (int p = 0; p < 6; p++) {
        int e4  = tid + 256 * p;       // 0..1535
        int row = e4 / 48;             // 0..31
        int cq  = (e4 % 48) << 2;      // 0..188 step 4
        const float* W = (cq < 64) ? Wq : (cq < 128 ? Wk : Wv);
        int cc2 = (cq < 64) ? cq : (cq < 128 ? cq - 64 : cq - 128);
        wr[p] = *(const float4*)(W + (size_t)row * HS + cc2);
    }

    for (int k0 = 0; k0 < CC; k0 += 32) {
        // store staged regs -> smem (tf32 convert)
        #pragma unroll
        for (int i = 0; i < 4; i++) {
            int e   = tid + 256 * i;
            int row = e >> 3;
            int c4  = (e & 7) << 2;
            u32* d = &Xs[row * XS_STRIDE + c4];
            d[0] = f2tf(xr[i].x); d[1] = f2tf(xr[i].y);
            d[2] = f2tf(xr[i].z); d[3] = f2tf(xr[i].w);
        }
        #pragma unroll
        for (int p = 0; p < 6; p++) {
            int e4  = tid + 256 * p;
            int row = e4 / 48;
            int cq  = (e4 % 48) << 2;
            u32* d = &Ws[row * WS_STRIDE + cq];
            d[0] = f2tf(wr[p].x); d[1] = f2tf(wr[p].y);
            d[2] = f2tf(wr[p].z); d[3] = f2tf(wr[p].w);
        }
        __syncthreads();

        // prefetch next tile (LDG latency overlaps MMAs below)
        if (k0 + 32 < CC) {
            int kn = k0 + 32;
            #pragma unroll
            for (int i = 0; i < 4; i++) {
                int e   = tid + 256 * i;
                int row = e >> 3;
                int c4  = (e & 7) << 2;
                xr[i] = *(const float4*)(x + (size_t)(rowbase + row) * CC + kn + c4);
            }
            #pragma unroll
            for (int p = 0; p < 6; p++) {
                int e4  = tid + 256 * p;
                int row = e4 / 48;
                int cq  = (e4 % 48) << 2;
                const float* W = (cq < 64) ? Wq : (cq < 128 ? Wk : Wv);
                int cc2 = (cq < 64) ? cq : (cq < 128 ? cq - 64 : cq - 128);
                wr[p] = *(const float4*)(W + (size_t)(kn + row) * HS + cc2);
            }
        }

        // compute: 4 k-steps of m16n8k8
        #pragma unroll
        for (int ks = 0; ks < 4; ks++) {
            u32 a[2][4];
            #pragma unroll
            for (int mt = 0; mt < 2; mt++) {
                int rb = wm * 32 + mt * 16;
                a[mt][0] = Xs[(rb + gid)     * XS_STRIDE + ks * 8 + tig];
                a[mt][1] = Xs[(rb + gid + 8) * XS_STRIDE + ks * 8 + tig];
                a[mt][2] = Xs[(rb + gid)     * XS_STRIDE + ks * 8 + tig + 4];
                a[mt][3] = Xs[(rb + gid + 8) * XS_STRIDE + ks * 8 + tig + 4];
            }
            #pragma unroll
            for (int nt = 0; nt < 12; nt++) {
                int col = wn * 96 + nt * 8 + gid;
                u32 b0 = Ws[(ks * 8 + tig)     * WS_STRIDE + col];
                u32 b1 = Ws[(ks * 8 + tig + 4) * WS_STRIDE + col];
                mma_tf32(acc[0][nt], a[0], b0, b1);
                mma_tf32(acc[1][nt], a[1], b0, b1);
            }
        }
        __syncthreads();
    }

    // epilogue: bias + scatter to g_q/g_k/g_v
    #pragma unroll
    for (int nt = 0; nt < 12; nt++) {
        int col = wn * 96 + nt * 8 + 2 * tig;     // 0..191 (warp-uniform branch per nt)
        float* outp; int c;
        const float* bias;
        if (col < 64)       { outp = g_q; c = col;       bias = bq; }
        else if (col < 128) { outp = g_k; c = col - 64;  bias = bk; }
        else                { outp = g_v; c = col - 128; bias = bv; }
        float b0 = bias[c], b1 = bias[c + 1];
        #pragma unroll
        for (int mt = 0; mt < 2; mt++) {
            int r0 = rowbase + wm * 32 + mt * 16 + gid;
            float2 v0 = make_float2(acc[mt][nt][0] + b0, acc[mt][nt][1] + b1);
            float2 v1 = make_float2(acc[mt][nt][2] + b0, acc[mt][nt][3] + b1);
            *(float2*)(outp + (size_t)r0 * HS + c)       = v0;
            *(float2*)(outp + (size_t)(r0 + 8) * HS + c) = v1;
        }
    }
}

// ---------------------------------------------------------------------------
// Flash attention with tf32 tensor-core MMA. (unchanged from R5 — 38.6us)
// Grid: (2 query blocks of 128, 256 batches). 8 warps x 16 query rows each.
// ---------------------------------------------------------------------------
#define KS_STRIDE 68
#define VS_STRIDE 72
#define PS_STRIDE 68
#define QS_STRIDE 68

__global__ __launch_bounds__(256) void attn_tc_kernel(float* __restrict__ out)
{
    extern __shared__ u32 sm[];
    u32* Ks = sm;                              // [64][68]
    u32* Vs = sm + 64 * KS_STRIDE;             // [64][72]
    u32* Ps = sm + 64 * KS_STRIDE + 64 * VS_STRIDE;  // [8][16][68]
    u32* Qs = sm;                              // staging [128][68] (overlaps Ks+Vs)

    const int tid  = threadIdx.x;
    const int wid  = tid >> 5;
    const int lane = tid & 31;
    const int gid  = lane >> 2;
    const int tig  = lane & 3;
    const int b  = blockIdx.y;
    const int qb = blockIdx.x;

    const float4* qg = (const float4*)(g_q + ((size_t)(b * TT) + qb * 128) * HS);
    #pragma unroll
    for (int i = 0; i < 8; i++) {
        int e   = tid + 256 * i;
        int row = e >> 4;
        int c4  = (e & 15) << 2;
        float4 v = qg[e];
        u32* d = &Qs[row * QS_STRIDE + c4];
        d[0] = f2tf(v.x * 0.125f); d[1] = f2tf(v.y * 0.125f);
        d[2] = f2tf(v.z * 0.125f); d[3] = f2tf(v.w * 0.125f);
    }
    __syncthreads();

    u32 qf[8][4];
    {
        int rb = wid * 16;
        #pragma unroll
        for (int k = 0; k < 8; k++) {
            qf[k][0] = Qs[(rb + gid)     * QS_STRIDE + k * 8 + tig];
            qf[k][1] = Qs[(rb + gid + 8) * QS_STRIDE + k * 8 + tig];
            qf[k][2] = Qs[(rb + gid)     * QS_STRIDE + k * 8 + tig + 4];
            qf[k][3] = Qs[(rb + gid + 8) * QS_STRIDE + k * 8 + tig + 4];
        }
    }
    __syncthreads();

    float o[8][4];
    #pragma unroll
    for (int j = 0; j < 8; j++)
        #pragma unroll
        for (int r = 0; r < 4; r++) o[j][r] = 0.f;

    float m0 = -1e30f, m1 = -1e30f, l0 = 0.f, l1 = 0.f;
    const int row0 = qb * 128 + wid * 16 + gid;
    const int row1 = row0 + 8;
    const int wrow_max = qb * 128 + wid * 16 + 15;

    const int nkb = 2 * qb + 2;
    for (int kb = 0; kb < nkb; kb++) {
        const int kbase = kb * 64;
        const float4* kg4 = (const float4*)(g_k + ((size_t)(b * TT) + kbase) * HS);
        const float4* vg4 = (const float4*)(g_v + ((size_t)(b * TT) + kbase) * HS);
        #pragma unroll
        for (int i = 0; i < 4; i++) {
            int e   = tid + 256 * i;
            int row = e >> 4;
            int c4  = (e & 15) << 2;
            float4 kv = kg4[e];
            u32* dk = &Ks[row * KS_STRIDE + c4];
            dk[0] = f2tf(kv.x); dk[1] = f2tf(kv.y); dk[2] = f2tf(kv.z); dk[3] = f2tf(kv.w);
            float4 vv = vg4[e];
            u32* dv = &Vs[row * VS_STRIDE + c4];
            dv[0] = f2tf(vv.x); dv[1] = f2tf(vv.y); dv[2] = f2tf(vv.z); dv[3] = f2tf(vv.w);
        }
        __syncthreads();

        if (kbase <= wrow_max) {
            float s[8][4];
            #pragma unroll
            for (int j = 0; j < 8; j++) {
                s[j][0] = s[j][1] = s[j][2] = s[j][3] = 0.f;
                #pragma unroll
                for (int k = 0; k < 8; k++) {
                    u32 b0 = Ks[(j * 8 + gid) * KS_STRIDE + k * 8 + tig];
                    u32 b1 = Ks[(j * 8 + gid) * KS_STRIDE + k * 8 + tig + 4];
                    mma_tf32(s[j], qf[k], b0, b1);
                }
            }
            if (kbase + 63 > row0) {
                #pragma unroll
                for (int j = 0; j < 8; j++) {
                    int key0 = kbase + j * 8 + 2 * tig;
                    int key1 = key0 + 1;
                    if (key0 > row0) s[j][0] = -1e30f;
                    if (key1 > row0) s[j][1] = -1e30f;
                    if (key0 > row1) s[j][2] = -1e30f;
                    if (key1 > row1) s[j][3] = -1e30f;
                }
            }
            float mx0 = -1e30f, mx1 = -1e30f;
            #pragma unroll
            for (int j = 0; j < 8; j++) {
                mx0 = fmaxf(mx0, fmaxf(s[j][0], s[j][1]));
                mx1 = fmaxf(mx1, fmaxf(s[j][2], s[j][3]));
            }
            mx0 = fmaxf(mx0, __shfl_xor_sync(0xffffffffu, mx0, 1));
            mx0 = fmaxf(mx0, __shfl_xor_sync(0xffffffffu, mx0, 2));
            mx1 = fmaxf(mx1, __shfl_xor_sync(0xffffffffu, mx1, 1));
            mx1 = fmaxf(mx1, __shfl_xor_sync(0xffffffffu, mx1, 2));

            float nm0 = fmaxf(m0, mx0), nm1 = fmaxf(m1, mx1);
            float cr0 = __expf(m0 - nm0), cr1 = __expf(m1 - nm1);
            m0 = nm0; m1 = nm1;

            u32* Pw = Ps + wid * 16 * PS_STRIDE;
            float sum0 = 0.f, sum1 = 0.f;
            #pragma unroll
            for (int j = 0; j < 8; j++) {
                float p0 = __expf(s[j][0] - nm0);
                float p1 = __expf(s[j][1] - nm0);
                float p2 = __expf(s[j][2] - nm1);
                float p3 = __expf(s[j][3] - nm1);
                sum0 += p0 + p1; sum1 += p2 + p3;
                int co = j * 8 + 2 * tig;
                Pw[gid * PS_STRIDE + co]           = f2tf(p0);
                Pw[gid * PS_STRIDE + co + 1]       = f2tf(p1);
                Pw[(gid + 8) * PS_STRIDE + co]     = f2tf(p2);
                Pw[(gid + 8) * PS_STRIDE + co + 1] = f2tf(p3);
            }
            sum0 += __shfl_xor_sync(0xffffffffu, sum0, 1);
            sum0 += __shfl_xor_sync(0xffffffffu, sum0, 2);
            sum1 += __shfl_xor_sync(0xffffffffu, sum1, 1);
            sum1 += __shfl_xor_sync(0xffffffffu, sum1, 2);
            l0 = l0 * cr0 + sum0;
            l1 = l1 * cr1 + sum1;

            #pragma unroll
            for (int j = 0; j < 8; j++) {
                o[j][0] *= cr0; o[j][1] *= cr0;
                o[j][2] *= cr1; o[j][3] *= cr1;
            }
            __syncwarp();

            #pragma unroll
            for (int kt = 0; kt < 8; kt++) {
                u32 a[4];
                a[0] = Pw[gid * PS_STRIDE + kt * 8 + tig];
                a[1] = Pw[(gid + 8) * PS_STRIDE + kt * 8 + tig];
                a[2] = Pw[gid * PS_STRIDE + kt * 8 + tig + 4];
                a[3] = Pw[(gid + 8) * PS_STRIDE + kt * 8 + tig + 4];
                #pragma unroll
                for (int j = 0; j < 8; j++) {
                    u32 b0 = Vs[(kt * 8 + tig)     * VS_STRIDE + j * 8 + gid];
                    u32 b1 = Vs[(kt * 8 + tig + 4) * VS_STRIDE + j * 8 + gid];
                    mma_tf32(o[j], a, b0, b1);
                }
            }
        }
        __syncthreads();
    }

    float inv0 = 1.f / l0, inv1 = 1.f / l1;
    #pragma unroll
    for (int j = 0; j < 8; j++) {
        int col = j * 8 + 2 * tig;
        float2 v0 = make_float2(o[j][0] * inv0, o[j][1] * inv0);
        float2 v1 = make_float2(o[j][2] * inv1, o[j][3] * inv1);
        *(float2*)(out + ((size_t)b * TT + row0) * HS + col) = v0;
        *(float2*)(out + ((size_t)b * TT + row1) * HS + col) = v1;
    }
}

extern "C" void kernel_launch(void* const* d_in, const int* in_sizes, int n_in,
                              void* d_out, int out_size)
{
    const float* x  = (const float*)d_in[0];
    const float* Wq = (const float*)d_in[1];
    const float* bq = (const float*)d_in[2];
    const float* Wk = (const float*)d_in[3];
    const float* bk = (const float*)d_in[4];
    const float* Wv = (const float*)d_in[5];
    const float* bv = (const float*)d_in[6];
    float* out = (float*)d_out;

    qkv_tc_kernel<<<BT / 128, 256>>>(x, Wq, bq, Wk, bk, Wv, bv);

    const int smem_bytes = (64 * KS_STRIDE + 64 * VS_STRIDE + 8 * 16 * PS_STRIDE) * 4;
    cudaFuncSetAttribute(attn_tc_kernel, cudaFuncAttributeMaxDynamicSharedMemorySize, smem_bytes);
    dim3 attn_grid(2, BB);
    attn_tc_kernel<<<attn_grid, 256, smem_bytes>>>(out);
}

// round 8
// speedup vs baseline: 4.3281x; 1.1411x over previous
#include <cuda_runtime.h>
#include <cuda_fp16.h>

#define BB 256
#define TT 256
#define CC 384
#define HS 64
#define BT (BB*TT)

typedef unsigned int u32;

// Scratch (allocation-free rule: __device__ globals)
__device__ float g_q[BT*HS];
__device__ float g_k[BT*HS];
__device__ float g_v[BT*HS];

// ---------------------------------------------------------------------------
// fp16 helpers
// ---------------------------------------------------------------------------
__device__ __forceinline__ u32 packh2(float a, float b) {
    __half2 h = __floats2half2_rn(a, b);
    return *(u32*)&h;
}

__device__ __forceinline__ void mma_f16(float c[4], u32 a0, u32 a1, u32 a2, u32 a3,
                                        u32 b0, u32 b1) {
    asm volatile(
        "mma.sync.aligned.m16n8k16.row.col.f32.f16.f16.f32 "
        "{%0,%1,%2,%3}, {%4,%5,%6,%7}, {%8,%9}, {%0,%1,%2,%3};\n"
        : "+f"(c[0]), "+f"(c[1]), "+f"(c[2]), "+f"(c[3])
        : "r"(a0), "r"(a1), "r"(a2), "r"(a3), "r"(b0), "r"(b1));
}

__device__ __forceinline__ void ldm_x4(u32& r0, u32& r1, u32& r2, u32& r3, u32 saddr) {
    asm volatile("ldmatrix.sync.aligned.m8n8.x4.shared.b16 {%0,%1,%2,%3}, [%4];"
                 : "=r"(r0), "=r"(r1), "=r"(r2), "=r"(r3) : "r"(saddr));
}

__device__ __forceinline__ void ldm_x4_t(u32& r0, u32& r1, u32& r2, u32& r3, u32 saddr) {
    asm volatile("ldmatrix.sync.aligned.m8n8.x4.trans.shared.b16 {%0,%1,%2,%3}, [%4];"
                 : "=r"(r0), "=r"(r1), "=r"(r2), "=r"(r3) : "r"(saddr));
}

// ---------------------------------------------------------------------------
// Fused QKV projection, fp16 m16n8k16. x read once.
// CTA tile 128x192, K-tile 32. 8 warps: 4(m) x 2(n), warp tile 32x96.
// Register-prefetch pipeline (packed half2 staging regs).
// Strides (u32): 20 and 100 -> == 4 (mod 32): conflict-free ldmatrix phases.
// ---------------------------------------------------------------------------
#define XS_ST 20    // 16 data u32 (32 halves) + 4 pad
#define WS_ST 100   // 96 data u32 (192 halves) + 4 pad

__global__ __launch_bounds__(256) void qkv_tc_kernel(
    const float* __restrict__ x,
    const float* __restrict__ Wq, const float* __restrict__ bq,
    const float* __restrict__ Wk, const float* __restrict__ bk,
    const float* __restrict__ Wv, const float* __restrict__ bv)
{
    __shared__ u32 Xs[128 * XS_ST];
    __shared__ u32 Ws[32 * WS_ST];

    const int tid  = threadIdx.x;
    const int wid  = tid >> 5;
    const int lane = tid & 31;
    const int tig  = lane & 3;
    const int l7   = lane & 7;
    const int t8   = lane >> 3;         // ldmatrix tile group 0..3
    const int wm   = wid >> 1;          // 0..3
    const int wn   = wid & 1;           // 0..1
    const int rowbase = blockIdx.x * 128;

    const u32 xs_base = (u32)__cvta_generic_to_shared(Xs);
    const u32 ws_base = (u32)__cvta_generic_to_shared(Ws);

    float acc[2][12][4];
    #pragma unroll
    for (int i = 0; i < 2; i++)
        #pragma unroll
        for (int j = 0; j < 12; j++)
            #pragma unroll
            for (int r = 0; r < 4; r++) acc[i][j][r] = 0.f;

    u32 xr[4][2], wr[6][2];   // packed half2 staging

    // prologue: load+convert first K-tile
    #pragma unroll
    for (int i = 0; i < 4; i++) {
        int e = tid + 256 * i;
        float4 v = *(const float4*)(x + (size_t)(rowbase + (e >> 3)) * CC + ((e & 7) << 2));
        xr[i][0] = packh2(v.x, v.y); xr[i][1] = packh2(v.z, v.w);
    }
    #pragma unroll
    for (int p = 0; p < 6; p++) {
        int e4  = tid + 256 * p;
        int row = e4 / 48;
        int cq  = (e4 % 48) << 2;
        const float* W = (cq < 64) ? Wq : (cq < 128 ? Wk : Wv);
        int cc2 = (cq < 64) ? cq : (cq < 128 ? cq - 64 : cq - 128);
        float4 v = *(const float4*)(W + (size_t)row * HS + cc2);
        wr[p][0] = packh2(v.x, v.y); wr[p][1] = packh2(v.z, v.w);
    }

    for (int k0 = 0; k0 < CC; k0 += 32) {
        // staged regs -> smem
        #pragma unroll
        for (int i = 0; i < 4; i++) {
            int e = tid + 256 * i;
            *(uint2*)&Xs[(e >> 3) * XS_ST + ((e & 7) << 1)] = make_uint2(xr[i][0], xr[i][1]);
        }
        #pragma unroll
        for (int p = 0; p < 6; p++) {
            int e4 = tid + 256 * p;
            *(uint2*)&Ws[(e4 / 48) * WS_ST + ((e4 % 48) << 1)] = make_uint2(wr[p][0], wr[p][1]);
        }
        __syncthreads();

        // prefetch next K-tile (hides LDG under MMAs)
        if (k0 + 32 < CC) {
            int kn = k0 + 32;
            #pragma unroll
            for (int i = 0; i < 4; i++) {
                int e = tid + 256 * i;
                float4 v = *(const float4*)(x + (size_t)(rowbase + (e >> 3)) * CC + kn + ((e & 7) << 2));
                xr[i][0] = packh2(v.x, v.y); xr[i][1] = packh2(v.z, v.w);
            }
            #pragma unroll
            for (int p = 0; p < 6; p++) {
                int e4  = tid + 256 * p;
                int row = e4 / 48;
                int cq  = (e4 % 48) << 2;
                const float* W = (cq < 64) ? Wq : (cq < 128 ? Wk : Wv);
                int cc2 = (cq < 64) ? cq : (cq < 128 ? cq - 64 : cq - 128);
                float4 v = *(const float4*)(W + (size_t)(kn + row) * HS + cc2);
                wr[p][0] = packh2(v.x, v.y); wr[p][1] = packh2(v.z, v.w);
            }
        }

        // compute: 2 k16-steps
        #pragma unroll
        for (int ks = 0; ks < 2; ks++) {
            u32 a[2][4];
            #pragma unroll
            for (int mt = 0; mt < 2; mt++) {
                u32 addr = xs_base + 4u * ((wm * 32 + mt * 16 + (t8 & 1) * 8 + l7) * XS_ST
                                           + ks * 8 + (t8 >> 1) * 4);
                ldm_x4(a[mt][0], a[mt][1], a[mt][2], a[mt][3], addr);
            }
            #pragma unroll
            for (int ntp = 0; ntp < 6; ntp++) {
                u32 b0, b1, b2, b3;
                u32 addr = ws_base + 4u * ((ks * 16 + (t8 & 1) * 8 + l7) * WS_ST
                                           + wn * 48 + (2 * ntp + (t8 >> 1)) * 4);
                ldm_x4_t(b0, b1, b2, b3, addr);   // Ws rows are k -> trans is correct here
                mma_f16(acc[0][2*ntp],   a[0][0], a[0][1], a[0][2], a[0][3], b0, b1);
                mma_f16(acc[1][2*ntp],   a[1][0], a[1][1], a[1][2], a[1][3], b0, b1);
                mma_f16(acc[0][2*ntp+1], a[0][0], a[0][1], a[0][2], a[0][3], b2, b3);
                mma_f16(acc[1][2*ntp+1], a[1][0], a[1][1], a[1][2], a[1][3], b2, b3);
            }
        }
        __syncthreads();
    }

    // epilogue: bias + scatter to g_q/g_k/g_v
    const int gid = lane >> 2;
    #pragma unroll
    for (int nt = 0; nt < 12; nt++) {
        int col = wn * 96 + nt * 8 + 2 * tig;
        float* outp; int c;
        const float* bias;
        if (col < 64)       { outp = g_q; c = col;       bias = bq; }
        else if (col < 128) { outp = g_k; c = col - 64;  bias = bk; }
        else                { outp = g_v; c = col - 128; bias = bv; }
        float b0 = bias[c], b1 = bias[c + 1];
        #pragma unroll
        for (int mt = 0; mt < 2; mt++) {
            int r0 = rowbase + wm * 32 + mt * 16 + gid;
            *(float2*)(outp + (size_t)r0 * HS + c) =
                make_float2(acc[mt][nt][0] + b0, acc[mt][nt][1] + b1);
            *(float2*)(outp + (size_t)(r0 + 8) * HS + c) =
                make_float2(acc[mt][nt][2] + b0, acc[mt][nt][3] + b1);
        }
    }
}

// ---------------------------------------------------------------------------
// Flash attention, fp16 m16n8k16. P stays in registers (k16 layout match).
// Grid: (2 query blocks of 128, 256 batches). 8 warps x 16 query rows.
// Smem 18.4KB -> 2 CTAs/SM.
// K (S=QK^T B-operand): NON-trans ldmatrix — smem rows are keys (= n dim).
// V (PV B-operand): trans ldmatrix — smem rows are keys (= k dim).
// ---------------------------------------------------------------------------
#define AS_ST 36   // 32 data u32 (64 halves) + 4 pad; 36 % 32 == 4

__global__ __launch_bounds__(256, 2) void attn_tc_kernel(float* __restrict__ out)
{
    extern __shared__ u32 sm[];
    u32* Ks = sm;                 // [64][36]
    u32* Vs = sm + 64 * AS_ST;    // [64][36]
    u32* Qs = sm;                 // staging [128][36] overlaps Ks+Vs exactly

    const int tid  = threadIdx.x;
    const int wid  = tid >> 5;
    const int lane = tid & 31;
    const int gid  = lane >> 2;
    const int tig  = lane & 3;
    const int l7   = lane & 7;
    const int t8   = lane >> 3;
    const int b  = blockIdx.y;
    const int qb = blockIdx.x;

    const u32 sm_base = (u32)__cvta_generic_to_shared(sm);
    const u32 ks_base = sm_base;
    const u32 vs_base = sm_base + 4u * 64 * AS_ST;

    // ---- stage Q (scaled, half2) ----
    const float4* qg = (const float4*)(g_q + ((size_t)(b * TT) + qb * 128) * HS);
    #pragma unroll
    for (int i = 0; i < 8; i++) {
        int e = tid + 256 * i;
        float4 v = qg[e];
        *(uint2*)&Qs[(e >> 4) * AS_ST + ((e & 15) << 1)] =
            make_uint2(packh2(v.x * 0.125f, v.y * 0.125f),
                       packh2(v.z * 0.125f, v.w * 0.125f));
    }
    __syncthreads();

    u32 qf[4][4];
    #pragma unroll
    for (int kt = 0; kt < 4; kt++) {
        u32 addr = sm_base + 4u * ((wid * 16 + (t8 & 1) * 8 + l7) * AS_ST
                                   + kt * 8 + (t8 >> 1) * 4);
        ldm_x4(qf[kt][0], qf[kt][1], qf[kt][2], qf[kt][3], addr);
    }
    __syncthreads();   // done with Q staging region

    float o[8][4];
    #pragma unroll
    for (int j = 0; j < 8; j++)
        #pragma unroll
        for (int r = 0; r < 4; r++) o[j][r] = 0.f;

    float m0 = -1e30f, m1 = -1e30f, l0 = 0.f, l1 = 0.f;
    const int row0 = qb * 128 + wid * 16 + gid;
    const int row1 = row0 + 8;
    const int wrow_max = qb * 128 + wid * 16 + 15;

    const int nkb = 2 * qb + 2;
    for (int kb = 0; kb < nkb; kb++) {
        const int kbase = kb * 64;
        const float4* kg4 = (const float4*)(g_k + ((size_t)(b * TT) + kbase) * HS);
        const float4* vg4 = (const float4*)(g_v + ((size_t)(b * TT) + kbase) * HS);
        #pragma unroll
        for (int i = 0; i < 4; i++) {
            int e = tid + 256 * i;
            int idx = (e >> 4) * AS_ST + ((e & 15) << 1);
            float4 kv = kg4[e];
            *(uint2*)&Ks[idx] = make_uint2(packh2(kv.x, kv.y), packh2(kv.z, kv.w));
            float4 vv = vg4[e];
            *(uint2*)&Vs[idx] = make_uint2(packh2(vv.x, vv.y), packh2(vv.z, vv.w));
        }
        __syncthreads();

        if (kbase <= wrow_max) {   // warp-uniform skip of fully-masked blocks
            // ---- S = Q K^T (16 x 64 per warp) ----
            float s[8][4];
            #pragma unroll
            for (int j = 0; j < 8; j++) {
                s[j][0] = s[j][1] = s[j][2] = s[j][3] = 0.f;
                u32 r0, r1, r2, r3;
                u32 arow = ks_base + 4u * ((j * 8 + l7) * AS_ST + t8 * 4);
                ldm_x4(r0, r1, r2, r3, arow);              // d 0..31 (NON-trans: rows=keys=n)
                mma_f16(s[j], qf[0][0], qf[0][1], qf[0][2], qf[0][3], r0, r1);
                mma_f16(s[j], qf[1][0], qf[1][1], qf[1][2], qf[1][3], r2, r3);
                ldm_x4(r0, r1, r2, r3, arow + 64u);        // d 32..63 (+16 u32)
                mma_f16(s[j], qf[2][0], qf[2][1], qf[2][2], qf[2][3], r0, r1);
                mma_f16(s[j], qf[3][0], qf[3][1], qf[3][2], qf[3][3], r2, r3);
            }
            // ---- causal mask ----
            if (kbase + 63 > row0) {
                #pragma unroll
                for (int j = 0; j < 8; j++) {
                    int key0 = kbase + j * 8 + 2 * tig;
                    int key1 = key0 + 1;
                    if (key0 > row0) s[j][0] = -1e30f;
                    if (key1 > row0) s[j][1] = -1e30f;
                    if (key0 > row1) s[j][2] = -1e30f;
                    if (key1 > row1) s[j][3] = -1e30f;
                }
            }
            // ---- online softmax ----
            float mx0 = -1e30f, mx1 = -1e30f;
            #pragma unroll
            for (int j = 0; j < 8; j++) {
                mx0 = fmaxf(mx0, fmaxf(s[j][0], s[j][1]));
                mx1 = fmaxf(mx1, fmaxf(s[j][2], s[j][3]));
            }
            mx0 = fmaxf(mx0, __shfl_xor_sync(0xffffffffu, mx0, 1));
            mx0 = fmaxf(mx0, __shfl_xor_sync(0xffffffffu, mx0, 2));
            mx1 = fmaxf(mx1, __shfl_xor_sync(0xffffffffu, mx1, 1));
            mx1 = fmaxf(mx1, __shfl_xor_sync(0xffffffffu, mx1, 2));

            float nm0 = fmaxf(m0, mx0), nm1 = fmaxf(m1, mx1);
            float cr0 = __expf(m0 - nm0), cr1 = __expf(m1 - nm1);
            m0 = nm0; m1 = nm1;

            u32 pa[8][2];    // P in registers: layout == A-fragment for PV
            float sum0 = 0.f, sum1 = 0.f;
            #pragma unroll
            for (int j = 0; j < 8; j++) {
                float p0 = __expf(s[j][0] - nm0);
                float p1 = __expf(s[j][1] - nm0);
                float p2 = __expf(s[j][2] - nm1);
                float p3 = __expf(s[j][3] - nm1);
                sum0 += p0 + p1; sum1 += p2 + p3;
                pa[j][0] = packh2(p0, p1);
                pa[j][1] = packh2(p2, p3);
            }
            sum0 += __shfl_xor_sync(0xffffffffu, sum0, 1);
            sum0 += __shfl_xor_sync(0xffffffffu, sum0, 2);
            sum1 += __shfl_xor_sync(0xffffffffu, sum1, 1);
            sum1 += __shfl_xor_sync(0xffffffffu, sum1, 2);
            l0 = l0 * cr0 + sum0;
            l1 = l1 * cr1 + sum1;

            #pragma unroll
            for (int j = 0; j < 8; j++) {
                o[j][0] *= cr0; o[j][1] *= cr0;
                o[j][2] *= cr1; o[j][3] *= cr1;
            }

            // ---- O += P V ----
            #pragma unroll
            for (int j = 0; j < 8; j++) {
                u32 r0, r1, r2, r3;
                u32 arow = vs_base + 4u * ((t8 * 8 + l7) * AS_ST + j * 4);
                ldm_x4_t(r0, r1, r2, r3, arow);                          // keys 0..31
                mma_f16(o[j], pa[0][0], pa[0][1], pa[1][0], pa[1][1], r0, r1);
                mma_f16(o[j], pa[2][0], pa[2][1], pa[3][0], pa[3][1], r2, r3);
                ldm_x4_t(r0, r1, r2, r3, arow + 4u * 32 * AS_ST);        // keys 32..63
                mma_f16(o[j], pa[4][0], pa[4][1], pa[5][0], pa[5][1], r0, r1);
                mma_f16(o[j], pa[6][0], pa[6][1], pa[7][0], pa[7][1], r2, r3);
            }
        }
        __syncthreads();
    }

    // ---- epilogue ----
    float inv0 = 1.f / l0, inv1 = 1.f / l1;
    #pragma unroll
    for (int j = 0; j < 8; j++) {
        int col = j * 8 + 2 * tig;
        *(float2*)(out + ((size_t)b * TT + row0) * HS + col) =
            make_float2(o[j][0] * inv0, o[j][1] * inv0);
        *(float2*)(out + ((size_t)b * TT + row1) * HS + col) =
            make_float2(o[j][2] * inv1, o[j][3] * inv1);
    }
}

extern "C" void kernel_launch(void* const* d_in, const int* in_sizes, int n_in,
                              void* d_out, int out_size)
{
    const float* x  = (const float*)d_in[0];
    const float* Wq = (const float*)d_in[1];
    const float* bq = (const float*)d_in[2];
    const float* Wk = (const float*)d_in[3];
    const float* bk = (const float*)d_in[4];
    const float* Wv = (const float*)d_in[5];
    const float* bv = (const float*)d_in[6];
    float* out = (float*)d_out;

    qkv_tc_kernel<<<BT / 128, 256>>>(x, Wq, bq, Wk, bk, Wv, bv);

    const int smem_bytes = 128 * AS_ST * 4;   // 18432 B (Q staging == K+V tiles)
    cudaFuncSetAttribute(attn_tc_kernel, cudaFuncAttributeMaxDynamicSharedMemorySize, smem_bytes);
    dim3 attn_grid(2, BB);
    attn_tc_kernel<<<attn_grid, 256, smem_bytes>>>(out);
}

// round 9
// speedup vs baseline: 4.6913x; 1.0839x over previous
#include <cuda_runtime.h>
#include <cuda_fp16.h>

#define BB 256
#define TT 256
#define CC 384
#define HS 64
#define BT (BB*TT)

typedef unsigned int u32;

// fp16 intermediates, packed half2 per u32: [row][32] u32 == [row][64] half
__device__ u32 g_qh[BT*32];
__device__ u32 g_kh[BT*32];
__device__ u32 g_vh[BT*32];

// ---------------------------------------------------------------------------
// fp16 helpers
// ---------------------------------------------------------------------------
__device__ __forceinline__ u32 packh2(float a, float b) {
    __half2 h = __floats2half2_rn(a, b);
    return *(u32*)&h;
}

__device__ __forceinline__ void mma_f16(float c[4], u32 a0, u32 a1, u32 a2, u32 a3,
                                        u32 b0, u32 b1) {
    asm volatile(
        "mma.sync.aligned.m16n8k16.row.col.f32.f16.f16.f32 "
        "{%0,%1,%2,%3}, {%4,%5,%6,%7}, {%8,%9}, {%0,%1,%2,%3};\n"
        : "+f"(c[0]), "+f"(c[1]), "+f"(c[2]), "+f"(c[3])
        : "r"(a0), "r"(a1), "r"(a2), "r"(a3), "r"(b0), "r"(b1));
}

__device__ __forceinline__ void ldm_x4(u32& r0, u32& r1, u32& r2, u32& r3, u32 saddr) {
    asm volatile("ldmatrix.sync.aligned.m8n8.x4.shared.b16 {%0,%1,%2,%3}, [%4];"
                 : "=r"(r0), "=r"(r1), "=r"(r2), "=r"(r3) : "r"(saddr));
}

__device__ __forceinline__ void ldm_x4_t(u32& r0, u32& r1, u32& r2, u32& r3, u32 saddr) {
    asm volatile("ldmatrix.sync.aligned.m8n8.x4.trans.shared.b16 {%0,%1,%2,%3}, [%4];"
                 : "=r"(r0), "=r"(r1), "=r"(r2), "=r"(r3) : "r"(saddr));
}

// ---------------------------------------------------------------------------
// Fused QKV projection, fp16 m16n8k16. x read once. fp16 packed outputs.
// CTA tile 128x192, K-tile 32, DOUBLE-BUFFERED smem, 512 threads.
// 16 warps: 4(m) x 4(n), warp tile 32x48 -> 48 acc regs/thread.
// Q output pre-scaled by 1/8 and biased; K/V biased.
// ---------------------------------------------------------------------------
#define XS_ST 20    // 16 data u32 (32 halves) + 4 pad ; 20 % 32 == 20
#define WS_ST 100   // 96 data u32 (192 halves) + 4 pad; 100 % 32 == 4

__global__ __launch_bounds__(512) void qkv_tc_kernel(
    const float* __restrict__ x,
    const float* __restrict__ Wq, const float* __restrict__ bq,
    const float* __restrict__ Wk, const float* __restrict__ bk,
    const float* __restrict__ Wv, const float* __restrict__ bv)
{
    __shared__ u32 Xs[2][128 * XS_ST];   // 2 x 10.2 KB
    __shared__ u32 Ws[2][32 * WS_ST];    // 2 x 12.8 KB

    const int tid  = threadIdx.x;
    const int wid  = tid >> 5;
    const int lane = tid & 31;
    const int tig  = lane & 3;
    const int gid  = lane >> 2;
    const int l7   = lane & 7;
    const int t8   = lane >> 3;
    const int wm   = wid >> 2;          // 0..3  (row group * 32)
    const int wn   = wid & 3;           // 0..3  (col group * 48)
    const int rowbase = blockIdx.x * 128;

    float acc[2][6][4];
    #pragma unroll
    for (int i = 0; i < 2; i++)
        #pragma unroll
        for (int j = 0; j < 6; j++)
            #pragma unroll
            for (int r = 0; r < 4; r++) acc[i][j][r] = 0.f;

    u32 xr[2][2], wr[3][2];   // packed half2 staging

    // ---- tile loaders (regs) ----
    auto ldg_tile = [&](int k0) {
        #pragma unroll
        for (int i = 0; i < 2; i++) {
            int e = tid + 512 * i;            // 0..1023 float4
            float4 v = *(const float4*)(x + (size_t)(rowbase + (e >> 3)) * CC + k0 + ((e & 7) << 2));
            xr[i][0] = packh2(v.x, v.y); xr[i][1] = packh2(v.z, v.w);
        }
        #pragma unroll
        for (int p = 0; p < 3; p++) {
            int e4  = tid + 512 * p;          // 0..1535 float4
            int row = e4 / 48;
            int cq  = (e4 % 48) << 2;
            const float* W = (cq < 64) ? Wq : (cq < 128 ? Wk : Wv);
            int cc2 = (cq < 64) ? cq : (cq < 128 ? cq - 64 : cq - 128);
            float4 v = *(const float4*)(W + (size_t)(k0 + row) * HS + cc2);
            wr[p][0] = packh2(v.x, v.y); wr[p][1] = packh2(v.z, v.w);
        }
    };
    auto sts_tile = [&](int buf) {
        #pragma unroll
        for (int i = 0; i < 2; i++) {
            int e = tid + 512 * i;
            *(uint2*)&Xs[buf][(e >> 3) * XS_ST + ((e & 7) << 1)] = make_uint2(xr[i][0], xr[i][1]);
        }
        #pragma unroll
        for (int p = 0; p < 3; p++) {
            int e4 = tid + 512 * p;
            *(uint2*)&Ws[buf][(e4 / 48) * WS_ST + ((e4 % 48) << 1)] = make_uint2(wr[p][0], wr[p][1]);
        }
    };

    // prologue
    ldg_tile(0);
    sts_tile(0);
    __syncthreads();

    const int NIT = CC / 32;   // 12
    for (int it = 0; it < NIT; it++) {
        const int cur = it & 1;
        if (it + 1 < NIT) ldg_tile((it + 1) * 32);   // overlaps MMAs below

        const u32 xs_base = (u32)__cvta_generic_to_shared(&Xs[cur][0]);
        const u32 ws_base = (u32)__cvta_generic_to_shared(&Ws[cur][0]);

        #pragma unroll
        for (int ks = 0; ks < 2; ks++) {
            u32 a[2][4];
            #pragma unroll
            for (int mt = 0; mt < 2; mt++) {
                u32 addr = xs_base + 4u * ((wm * 32 + mt * 16 + (t8 & 1) * 8 + l7) * XS_ST
                                           + ks * 8 + (t8 >> 1) * 4);
                ldm_x4(a[mt][0], a[mt][1], a[mt][2], a[mt][3], addr);
            }
            #pragma unroll
            for (int ntp = 0; ntp < 3; ntp++) {
                u32 b0, b1, b2, b3;
                u32 addr = ws_base + 4u * ((ks * 16 + (t8 & 1) * 8 + l7) * WS_ST
                                           + wn * 24 + (2 * ntp + (t8 >> 1)) * 4);
                ldm_x4_t(b0, b1, b2, b3, addr);
                mma_f16(acc[0][2*ntp],   a[0][0], a[0][1], a[0][2], a[0][3], b0, b1);
                mma_f16(acc[1][2*ntp],   a[1][0], a[1][1], a[1][2], a[1][3], b0, b1);
                mma_f16(acc[0][2*ntp+1], a[0][0], a[0][1], a[0][2], a[0][3], b2, b3);
                mma_f16(acc[1][2*ntp+1], a[1][0], a[1][1], a[1][2], a[1][3], b2, b3);
            }
        }

        if (it + 1 < NIT) sts_tile(1 - cur);
        __syncthreads();
    }

    // epilogue: bias (+Q scale), pack to half2, scatter
    #pragma unroll
    for (int nt = 0; nt < 6; nt++) {
        int col = wn * 48 + nt * 8 + 2 * tig;        // half index 0..191
        int hcol = (wn * 48 + nt * 8) / 2 + tig;     // u32 index 0..95
        u32* outp; int hc; const float* bias; float sc;
        if (col < 64)       { outp = g_qh; hc = hcol;      bias = bq; sc = 0.125f; }
        else if (col < 128) { outp = g_kh; hc = hcol - 32; bias = bk; sc = 1.f; }
        else                { outp = g_vh; hc = hcol - 64; bias = bv; sc = 1.f; }
        int c = col & 63;
        float b0 = bias[c], b1 = bias[c + 1];
        #pragma unroll
        for (int mt = 0; mt < 2; mt++) {
            int r0 = rowbase + wm * 32 + mt * 16 + gid;
            outp[(size_t)r0 * 32 + hc]       = packh2((acc[mt][nt][0] + b0) * sc,
                                                      (acc[mt][nt][1] + b1) * sc);
            outp[(size_t)(r0 + 8) * 32 + hc] = packh2((acc[mt][nt][2] + b0) * sc,
                                                      (acc[mt][nt][3] + b1) * sc);
        }
    }
}

// ---------------------------------------------------------------------------
// Flash attention, fp16 m16n8k16. Inputs already fp16-packed & Q pre-scaled:
// staging is pure uint4 copies (no converts). P stays in registers.
// Grid: (2 query blocks of 128, 256 batches). 8 warps x 16 query rows.
// ---------------------------------------------------------------------------
#define AS_ST 36   // 32 data u32 (64 halves) + 4 pad; 36 % 32 == 4

__global__ __launch_bounds__(256, 2) void attn_tc_kernel(float* __restrict__ out)
{
    extern __shared__ u32 sm[];
    u32* Ks = sm;                 // [64][36]
    u32* Vs = sm + 64 * AS_ST;    // [64][36]
    u32* Qs = sm;                 // staging [128][36] overlaps Ks+Vs exactly

    const int tid  = threadIdx.x;
    const int wid  = tid >> 5;
    const int lane = tid & 31;
    const int gid  = lane >> 2;
    const int tig  = lane & 3;
    const int l7   = lane & 7;
    const int t8   = lane >> 3;
    const int b  = blockIdx.y;
    const int qb = blockIdx.x;

    const u32 sm_base = (u32)__cvta_generic_to_shared(sm);
    const u32 ks_base = sm_base;
    const u32 vs_base = sm_base + 4u * 64 * AS_ST;

    // ---- stage Q: straight uint4 copy ----
    const uint4* qg = (const uint4*)(g_qh + (size_t)(b * TT + qb * 128) * 32);
    #pragma unroll
    for (int i = 0; i < 4; i++) {
        int e = tid + 256 * i;        // 0..1023 uint4 (128 rows x 8)
        *(uint4*)&Qs[(e >> 3) * AS_ST + (e & 7) * 4] = qg[e];
    }
    __syncthreads();

    u32 qf[4][4];
    #pragma unroll
    for (int kt = 0; kt < 4; kt++) {
        u32 addr = sm_base + 4u * ((wid * 16 + (t8 & 1) * 8 + l7) * AS_ST
                                   + kt * 8 + (t8 >> 1) * 4);
        ldm_x4(qf[kt][0], qf[kt][1], qf[kt][2], qf[kt][3], addr);
    }
    __syncthreads();   // done with Q staging region

    float o[8][4];
    #pragma unroll
    for (int j = 0; j < 8; j++)
        #pragma unroll
        for (int r = 0; r < 4; r++) o[j][r] = 0.f;

    float m0 = -1e30f, m1 = -1e30f, l0 = 0.f, l1 = 0.f;
    const int row0 = qb * 128 + wid * 16 + gid;
    const int row1 = row0 + 8;
    const int wrow_max = qb * 128 + wid * 16 + 15;

    const int nkb = 2 * qb + 2;
    for (int kb = 0; kb < nkb; kb++) {
        const int kbase = kb * 64;
        const uint4* kg4 = (const uint4*)(g_kh + (size_t)(b * TT + kbase) * 32);
        const uint4* vg4 = (const uint4*)(g_vh + (size_t)(b * TT + kbase) * 32);
        #pragma unroll
        for (int i = 0; i < 2; i++) {
            int e = tid + 256 * i;    // 0..511 uint4 (64 rows x 8)
            int idx = (e >> 3) * AS_ST + (e & 7) * 4;
            *(uint4*)&Ks[idx] = kg4[e];
            *(uint4*)&Vs[idx] = vg4[e];
        }
        __syncthreads();

        if (kbase <= wrow_max) {   // warp-uniform skip of fully-masked blocks
            // ---- S = Q K^T (16 x 64 per warp) ----
            float s[8][4];
            #pragma unroll
            for (int j = 0; j < 8; j++) {
                s[j][0] = s[j][1] = s[j][2] = s[j][3] = 0.f;
                u32 r0, r1, r2, r3;
                u32 arow = ks_base + 4u * ((j * 8 + l7) * AS_ST + t8 * 4);
                ldm_x4(r0, r1, r2, r3, arow);              // d 0..31 (rows=keys=n)
                mma_f16(s[j], qf[0][0], qf[0][1], qf[0][2], qf[0][3], r0, r1);
                mma_f16(s[j], qf[1][0], qf[1][1], qf[1][2], qf[1][3], r2, r3);
                ldm_x4(r0, r1, r2, r3, arow + 64u);        // d 32..63
                mma_f16(s[j], qf[2][0], qf[2][1], qf[2][2], qf[2][3], r0, r1);
                mma_f16(s[j], qf[3][0], qf[3][1], qf[3][2], qf[3][3], r2, r3);
            }
            // ---- causal mask ----
            if (kbase + 63 > row0) {
                #pragma unroll
                for (int j = 0; j < 8; j++) {
                    int key0 = kbase + j * 8 + 2 * tig;
                    int key1 = key0 + 1;
                    if (key0 > row0) s[j][0] = -1e30f;
                    if (key1 > row0) s[j][1] = -1e30f;
                    if (key0 > row1) s[j][2] = -1e30f;
                    if (key1 > row1) s[j][3] = -1e30f;
                }
            }
            // ---- online softmax ----
            float mx0 = -1e30f, mx1 = -1e30f;
            #pragma unroll
            for (int j = 0; j < 8; j++) {
                mx0 = fmaxf(mx0, fmaxf(s[j][0], s[j][1]));
                mx1 = fmaxf(mx1, fmaxf(s[j][2], s[j][3]));
            }
            mx0 = fmaxf(mx0, __shfl_xor_sync(0xffffffffu, mx0, 1));
            mx0 = fmaxf(mx0, __shfl_xor_sync(0xffffffffu, mx0, 2));
            mx1 = fmaxf(mx1, __shfl_xor_sync(0xffffffffu, mx1, 1));
            mx1 = fmaxf(mx1, __shfl_xor_sync(0xffffffffu, mx1, 2));

            float nm0 = fmaxf(m0, mx0), nm1 = fmaxf(m1, mx1);
            float cr0 = __expf(m0 - nm0), cr1 = __expf(m1 - nm1);
            m0 = nm0; m1 = nm1;

            u32 pa[8][2];    // P in registers: layout == A-fragment for PV
            float sum0 = 0.f, sum1 = 0.f;
            #pragma unroll
            for (int j = 0; j < 8; j++) {
                float p0 = __expf(s[j][0] - nm0);
                float p1 = __expf(s[j][1] - nm0);
                float p2 = __expf(s[j][2] - nm1);
                float p3 = __expf(s[j][3] - nm1);
                sum0 += p0 + p1; sum1 += p2 + p3;
                pa[j][0] = packh2(p0, p1);
                pa[j][1] = packh2(p2, p3);
            }
            sum0 += __shfl_xor_sync(0xffffffffu, sum0, 1);
            sum0 += __shfl_xor_sync(0xffffffffu, sum0, 2);
            sum1 += __shfl_xor_sync(0xffffffffu, sum1, 1);
            sum1 += __shfl_xor_sync(0xffffffffu, sum1, 2);
            l0 = l0 * cr0 + sum0;
            l1 = l1 * cr1 + sum1;

            #pragma unroll
            for (int j = 0; j < 8; j++) {
                o[j][0] *= cr0; o[j][1] *= cr0;
                o[j][2] *= cr1; o[j][3] *= cr1;
            }

            // ---- O += P V ----
            #pragma unroll
            for (int j = 0; j < 8; j++) {
                u32 r0, r1, r2, r3;
                u32 arow = vs_base + 4u * ((t8 * 8 + l7) * AS_ST + j * 4);
                ldm_x4_t(r0, r1, r2, r3, arow);                          // keys 0..31
                mma_f16(o[j], pa[0][0], pa[0][1], pa[1][0], pa[1][1], r0, r1);
                mma_f16(o[j], pa[2][0], pa[2][1], pa[3][0], pa[3][1], r2, r3);
                ldm_x4_t(r0, r1, r2, r3, arow + 4u * 32 * AS_ST);        // keys 32..63
                mma_f16(o[j], pa[4][0], pa[4][1], pa[5][0], pa[5][1], r0, r1);
                mma_f16(o[j], pa[6][0], pa[6][1], pa[7][0], pa[7][1], r2, r3);
            }
        }
        __syncthreads();
    }

    // ---- epilogue ----
    float inv0 = 1.f / l0, inv1 = 1.f / l1;
    #pragma unroll
    for (int j = 0; j < 8; j++) {
        int col = j * 8 + 2 * tig;
        *(float2*)(out + ((size_t)b * TT + row0) * HS + col) =
            make_float2(o[j][0] * inv0, o[j][1] * inv0);
        *(float2*)(out + ((size_t)b * TT + row1) * HS + col) =
            make_float2(o[j][2] * inv1, o[j][3] * inv1);
    }
}

extern "C" void kernel_launch(void* const* d_in, const int* in_sizes, int n_in,
                              void* d_out, int out_size)
{
    const float* x  = (const float*)d_in[0];
    const float* Wq = (const float*)d_in[1];
    const float* bq = (const float*)d_in[2];
    const float* Wk = (const float*)d_in[3];
    const float* bk = (const float*)d_in[4];
    const float* Wv = (const float*)d_in[5];
    const float* bv = (const float*)d_in[6];
    float* out = (float*)d_out;

    qkv_tc_kernel<<<BT / 128, 512>>>(x, Wq, bq, Wk, bk, Wv, bv);

    const int smem_bytes = 128 * AS_ST * 4;   // 18432 B
    cudaFuncSetAttribute(attn_tc_kernel, cudaFuncAttributeMaxDynamicSharedMemorySize, smem_bytes);
    dim3 attn_grid(2, BB);
    attn_tc_kernel<<<attn_grid, 256, smem_bytes>>>(out);
}

// round 11
// speedup vs baseline: 4.7961x; 1.0223x over previous
#include <cuda_runtime.h>
#include <cuda_fp16.h>

#define BB 256
#define TT 256
#define CC 384
#define HS 64
#define BT (BB*TT)

typedef unsigned int u32;

// fp16 intermediates, packed half2 per u32: [row][32] u32 == [row][64] half
__device__ u32 g_qh[BT*32];
__device__ u32 g_kh[BT*32];
__device__ u32 g_vh[BT*32];
// fp16 image of W = [384 k][192 n] as half2-packed u32: [384][96]
__device__ u32 g_wimg[384*96];

// ---------------------------------------------------------------------------
// helpers
// ---------------------------------------------------------------------------
__device__ __forceinline__ u32 packh2(float a, float b) {
    __half2 h = __floats2half2_rn(a, b);
    return *(u32*)&h;
}

__device__ __forceinline__ void mma_f16(float c[4], u32 a0, u32 a1, u32 a2, u32 a3,
                                        u32 b0, u32 b1) {
    asm volatile(
        "mma.sync.aligned.m16n8k16.row.col.f32.f16.f16.f32 "
        "{%0,%1,%2,%3}, {%4,%5,%6,%7}, {%8,%9}, {%0,%1,%2,%3};\n"
        : "+f"(c[0]), "+f"(c[1]), "+f"(c[2]), "+f"(c[3])
        : "r"(a0), "r"(a1), "r"(a2), "r"(a3), "r"(b0), "r"(b1));
}
__device__ __forceinline__ void ldm_x4(u32& r0, u32& r1, u32& r2, u32& r3, u32 saddr) {
    asm volatile("ldmatrix.sync.aligned.m8n8.x4.shared.b16 {%0,%1,%2,%3}, [%4];"
                 : "=r"(r0), "=r"(r1), "=r"(r2), "=r"(r3) : "r"(saddr));
}
__device__ __forceinline__ void ldm_x4_t(u32& r0, u32& r1, u32& r2, u32& r3, u32 saddr) {
    asm volatile("ldmatrix.sync.aligned.m8n8.x4.trans.shared.b16 {%0,%1,%2,%3}, [%4];"
                 : "=r"(r0), "=r"(r1), "=r"(r2), "=r"(r3) : "r"(saddr));
}
__device__ __forceinline__ void cp_async16(u32 dst, const void* src) {
    asm volatile("cp.async.cg.shared.global [%0], [%1], 16;" :: "r"(dst), "l"(src) : "memory");
}
#define CP_ASYNC_WAIT_ALL() asm volatile("cp.async.wait_all;" ::: "memory")

// ---------------------------------------------------------------------------
// prep: W (fp32, [k][64] x3) -> g_wimg fp16 half2 [384 k][96 u32] (n-major)
// ---------------------------------------------------------------------------
__global__ __launch_bounds__(256) void prep_kernel(
    const float* __restrict__ Wq, const float* __restrict__ Wk,
    const float* __restrict__ Wv)
{
    int idx = blockIdx.x * 256 + threadIdx.x;   // 0..36863
    int k = idx / 96;
    int c = idx % 96;
    int n = 2 * c;                               // 0..190 (even)
    const float* W = (n < 64) ? Wq : (n < 128 ? Wk : Wv);
    int col = n & 63;
    float2 v = *(const float2*)(W + (size_t)k * HS + col);
    g_wimg[idx] = packh2(v.x, v.y);
}

// no-op: shifts ncu launch-slot so qkv gets profiled
__global__ void probe_kernel() {}

// ---------------------------------------------------------------------------
// Fused QKV projection, fp16 m16n8k16. x read once; W smem-resident (staged
// ONCE per CTA via bulk cp.async from pre-converted fp16 image).
// CTA tile 128x192, K-tile 32 (x double-buffered), 512 threads.
// 16 warps: 4(m) x 4(n), warp tile 32x48.
// Dynamic smem: W [384][100] u32 = 153.6KB | x0 [128][20] | x1 [128][20]
// ---------------------------------------------------------------------------
#define XS_ST 20
#define WS_ST 100
#define QKV_W_U32   (384 * WS_ST)              // 38400
#define QKV_X_U32   (128 * XS_ST)              // 2560
#define QKV_DSMEM   ((QKV_W_U32 + 2 * QKV_X_U32) * 4)   // 174,080 B

__global__ __launch_bounds__(512) void qkv_tc_kernel(
    const float* __restrict__ x,
    const float* __restrict__ bq, const float* __restrict__ bk,
    const float* __restrict__ bv)
{
    extern __shared__ u32 dsm[];
    u32* Wsm = dsm;                             // [384][100]
    u32* Xs[2] = { dsm + QKV_W_U32, dsm + QKV_W_U32 + QKV_X_U32 };

    const int tid  = threadIdx.x;
    const int wid  = tid >> 5;
    const int lane = tid & 31;
    const int tig  = lane & 3;
    const int gid  = lane >> 2;
    const int l7   = lane & 7;
    const int t8   = lane >> 3;
    const int wm   = wid >> 2;          // 0..3  (row group * 32)
    const int wn   = wid & 3;           // 0..3  (col group * 48)
    const int rowbase = blockIdx.x * 128;

    const u32 ws_base = (u32)__cvta_generic_to_shared(Wsm);
    const u32 xs_base[2] = { (u32)__cvta_generic_to_shared(Xs[0]),
                             (u32)__cvta_generic_to_shared(Xs[1]) };

    // ---- stage ALL of W via cp.async: 9216 uint4 (rows of 24, pad to 25) ----
    #pragma unroll
    for (int i = 0; i < 18; i++) {
        int e   = tid + 512 * i;        // 0..9215
        int row = e / 24;
        int j   = e % 24;
        cp_async16(ws_base + 4u * (row * WS_ST + j * 4), &g_wimg[row * 96 + j * 4]);
    }

    float acc[2][6][4];
    #pragma unroll
    for (int i = 0; i < 2; i++)
        #pragma unroll
        for (int j = 0; j < 6; j++)
            #pragma unroll
            for (int r = 0; r < 4; r++) acc[i][j][r] = 0.f;

    u32 xr[2][2];   // packed half2 staging for x

    auto ldg_x = [&](int k0) {
        #pragma unroll
        for (int i = 0; i < 2; i++) {
            int e = tid + 512 * i;            // 0..1023 float4
            float4 v = *(const float4*)(x + (size_t)(rowbase + (e >> 3)) * CC + k0 + ((e & 7) << 2));
            xr[i][0] = packh2(v.x, v.y); xr[i][1] = packh2(v.z, v.w);
        }
    };
    auto sts_x = [&](int buf) {
        #pragma unroll
        for (int i = 0; i < 2; i++) {
            int e = tid + 512 * i;
            *(uint2*)&Xs[buf][(e >> 3) * XS_ST + ((e & 7) << 1)] = make_uint2(xr[i][0], xr[i][1]);
        }
    };

    // prologue: x tile 0 + wait for W
    ldg_x(0);
    sts_x(0);
    CP_ASYNC_WAIT_ALL();
    __syncthreads();

    const int NIT = CC / 32;   // 12
    for (int it = 0; it < NIT; it++) {
        const int cur = it & 1;
        if (it + 1 < NIT) ldg_x((it + 1) * 32);   // overlaps MMAs below

        #pragma unroll
        for (int ks = 0; ks < 2; ks++) {
            const int krow = it * 32 + ks * 16;   // W smem row base for this k16
            u32 a[2][4];
            #pragma unroll
            for (int mt = 0; mt < 2; mt++) {
                u32 addr = xs_base[cur] + 4u * ((wm * 32 + mt * 16 + (t8 & 1) * 8 + l7) * XS_ST
                                                + ks * 8 + (t8 >> 1) * 4);
                ldm_x4(a[mt][0], a[mt][1], a[mt][2], a[mt][3], addr);
            }
            #pragma unroll
            for (int ntp = 0; ntp < 3; ntp++) {
                u32 b0, b1, b2, b3;
                u32 addr = ws_base + 4u * ((krow + (t8 & 1) * 8 + l7) * WS_ST
                                           + wn * 24 + (2 * ntp + (t8 >> 1)) * 4);
                ldm_x4_t(b0, b1, b2, b3, addr);
                mma_f16(acc[0][2*ntp],   a[0][0], a[0][1], a[0][2], a[0][3], b0, b1);
                mma_f16(acc[1][2*ntp],   a[1][0], a[1][1], a[1][2], a[1][3], b0, b1);
                mma_f16(acc[0][2*ntp+1], a[0][0], a[0][1], a[0][2], a[0][3], b2, b3);
                mma_f16(acc[1][2*ntp+1], a[1][0], a[1][1], a[1][2], a[1][3], b2, b3);
            }
        }

        if (it + 1 < NIT) sts_x(1 - cur);
        __syncthreads();
    }

    // epilogue: bias (+Q scale), pack to half2, scatter
    #pragma unroll
    for (int nt = 0; nt < 6; nt++) {
        int col = wn * 48 + nt * 8 + 2 * tig;        // half index 0..191
        int hcol = (wn * 48 + nt * 8) / 2 + tig;     // u32 index 0..95
        u32* outp; int hc; const float* bias; float sc;
        if (col < 64)       { outp = g_qh; hc = hcol;      bias = bq; sc = 0.125f; }
        else if (col < 128) { outp = g_kh; hc = hcol - 32; bias = bk; sc = 1.f; }
        else                { outp = g_vh; hc = hcol - 64; bias = bv; sc = 1.f; }
        int c = col & 63;
        float b0 = bias[c], b1 = bias[c + 1];
        #pragma unroll
        for (int mt = 0; mt < 2; mt++) {
            int r0 = rowbase + wm * 32 + mt * 16 + gid;
            outp[(size_t)r0 * 32 + hc]       = packh2((acc[mt][nt][0] + b0) * sc,
                                                      (acc[mt][nt][1] + b1) * sc);
            outp[(size_t)(r0 + 8) * 32 + hc] = packh2((acc[mt][nt][2] + b0) * sc,
                                                      (acc[mt][nt][3] + b1) * sc);
        }
    }
}

// ---------------------------------------------------------------------------
// Flash attention, fp16 m16n8k16 (unchanged from R9 — 25.8us, passing).
// ---------------------------------------------------------------------------
#define AS_ST 36

__global__ __launch_bounds__(256, 2) void attn_tc_kernel(float* __restrict__ out)
{
    extern __shared__ u32 sm[];
    u32* Ks = sm;
    u32* Vs = sm + 64 * AS_ST;
    u32* Qs = sm;

    const int tid  = threadIdx.x;
    const int wid  = tid >> 5;
    const int lane = tid & 31;
    const int gid  = lane >> 2;
    const int tig  = lane & 3;
    const int l7   = lane & 7;
    const int t8   = lane >> 3;
    const int b  = blockIdx.y;
    const int qb = blockIdx.x;

    const u32 sm_base = (u32)__cvta_generic_to_shared(sm);
    const u32 ks_base = sm_base;
    const u32 vs_base = sm_base + 4u * 64 * AS_ST;

    const uint4* qg = (const uint4*)(g_qh + (size_t)(b * TT + qb * 128) * 32);
    #pragma unroll
    for (int i = 0; i < 4; i++) {
        int e = tid + 256 * i;
        *(uint4*)&Qs[(e >> 3) * AS_ST + (e & 7) * 4] = qg[e];
    }
    __syncthreads();

    u32 qf[4][4];
    #pragma unroll
    for (int kt = 0; kt < 4; kt++) {
        u32 addr = sm_base + 4u * ((wid * 16 + (t8 & 1) * 8 + l7) * AS_ST
                                   + kt * 8 + (t8 >> 1) * 4);
        ldm_x4(qf[kt][0], qf[kt][1], qf[kt][2], qf[kt][3], addr);
    }
    __syncthreads();

    float o[8][4];
    #pragma unroll
    for (int j = 0; j < 8; j++)
        #pragma unroll
        for (int r = 0; r < 4; r++) o[j][r] = 0.f;

    float m0 = -1e30f, m1 = -1e30f, l0 = 0.f, l1 = 0.f;
    const int row0 = qb * 128 + wid * 16 + gid;
    const int row1 = row0 + 8;
    const int wrow_max = qb * 128 + wid * 16 + 15;

    const int nkb = 2 * qb + 2;
    for (int kb = 0; kb < nkb; kb++) {
        const int kbase = kb * 64;
        const uint4* kg4 = (const uint4*)(g_kh + (size_t)(b * TT + kbase) * 32);
        const uint4* vg4 = (const uint4*)(g_vh + (size_t)(b * TT + kbase) * 32);
        #pragma unroll
        for (int i = 0; i < 2; i++) {
            int e = tid + 256 * i;
            int idx = (e >> 3) * AS_ST + (e & 7) * 4;
            *(uint4*)&Ks[idx] = kg4[e];
            *(uint4*)&Vs[idx] = vg4[e];
        }
        __syncthreads();

        if (kbase <= wrow_max) {
            float s[8][4];
            #pragma unroll
            for (int j = 0; j < 8; j++) {
                s[j][0] = s[j][1] = s[j][2] = s[j][3] = 0.f;
                u32 r0, r1, r2, r3;
                u32 arow = ks_base + 4u * ((j * 8 + l7) * AS_ST + t8 * 4);
                ldm_x4(r0, r1, r2, r3, arow);
                mma_f16(s[j], qf[0][0], qf[0][1], qf[0][2], qf[0][3], r0, r1);
                mma_f16(s[j], qf[1][0], qf[1][1], qf[1][2], qf[1][3], r2, r3);
                ldm_x4(r0, r1, r2, r3, arow + 64u);
                mma_f16(s[j], qf[2][0], qf[2][1], qf[2][2], qf[2][3], r0, r1);
                mma_f16(s[j], qf[3][0], qf[3][1], qf[3][2], qf[3][3], r2, r3);
            }
            if (kbase + 63 > row0) {
                #pragma unroll
                for (int j = 0; j < 8; j++) {
                    int key0 = kbase + j * 8 + 2 * tig;
                    int key1 = key0 + 1;
                    if (key0 > row0) s[j][0] = -1e30f;
                    if (key1 > row0) s[j][1] = -1e30f;
                    if (key0 > row1) s[j][2] = -1e30f;
                    if (key1 > row1) s[j][3] = -1e30f;
                }
            }
            float mx0 = -1e30f, mx1 = -1e30f;
            #pragma unroll
            for (int j = 0; j < 8; j++) {
                mx0 = fmaxf(mx0, fmaxf(s[j][0], s[j][1]));
                mx1 = fmaxf(mx1, fmaxf(s[j][2], s[j][3]));
            }
            mx0 = fmaxf(mx0, __shfl_xor_sync(0xffffffffu, mx0, 1));
            mx0 = fmaxf(mx0, __shfl_xor_sync(0xffffffffu, mx0, 2));
            mx1 = fmaxf(mx1, __shfl_xor_sync(0xffffffffu, mx1, 1));
            mx1 = fmaxf(mx1, __shfl_xor_sync(0xffffffffu, mx1, 2));

            float nm0 = fmaxf(m0, mx0), nm1 = fmaxf(m1, mx1);
            float cr0 = __expf(m0 - nm0), cr1 = __expf(m1 - nm1);
            m0 = nm0; m1 = nm1;

            u32 pa[8][2];
            float sum0 = 0.f, sum1 = 0.f;
            #pragma unroll
            for (int j = 0; j < 8; j++) {
                float p0 = __expf(s[j][0] - nm0);
                float p1 = __expf(s[j][1] - nm0);
                float p2 = __expf(s[j][2] - nm1);
                float p3 = __expf(s[j][3] - nm1);
                sum0 += p0 + p1; sum1 += p2 + p3;
                pa[j][0] = packh2(p0, p1);
                pa[j][1] = packh2(p2, p3);
            }
            sum0 += __shfl_xor_sync(0xffffffffu, sum0, 1);
            sum0 += __shfl_xor_sync(0xffffffffu, sum0, 2);
            sum1 += __shfl_xor_sync(0xffffffffu, sum1, 1);
            sum1 += __shfl_xor_sync(0xffffffffu, sum1, 2);
            l0 = l0 * cr0 + sum0;
            l1 = l1 * cr1 + sum1;

            #pragma unroll
            for (int j = 0; j < 8; j++) {
                o[j][0] *= cr0; o[j][1] *= cr0;
                o[j][2] *= cr1; o[j][3] *= cr1;
            }

            #pragma unroll
            for (int j = 0; j < 8; j++) {
                u32 r0, r1, r2, r3;
                u32 arow = vs_base + 4u * ((t8 * 8 + l7) * AS_ST + j * 4);
                ldm_x4_t(r0, r1, r2, r3, arow);
                mma_f16(o[j], pa[0][0], pa[0][1], pa[1][0], pa[1][1], r0, r1);
                mma_f16(o[j], pa[2][0], pa[2][1], pa[3][0], pa[3][1], r2, r3);
                ldm_x4_t(r0, r1, r2, r3, arow + 4u * 32 * AS_ST);
                mma_f16(o[j], pa[4][0], pa[4][1], pa[5][0], pa[5][1], r0, r1);
                mma_f16(o[j], pa[6][0], pa[6][1], pa[7][0], pa[7][1], r2, r3);
            }
        }
        __syncthreads();
    }

    float inv0 = 1.f / l0, inv1 = 1.f / l1;
    #pragma unroll
    for (int j = 0; j < 8; j++) {
        int col = j * 8 + 2 * tig;
        *(float2*)(out + ((size_t)b * TT + row0) * HS + col) =
            make_float2(o[j][0] * inv0, o[j][1] * inv0);
        *(float2*)(out + ((size_t)b * TT + row1) * HS + col) =
            make_float2(o[j][2] * inv1, o[j][3] * inv1);
    }
}

extern "C" void kernel_launch(void* const* d_in, const int* in_sizes, int n_in,
                              void* d_out, int out_size)
{
    const float* x  = (const float*)d_in[0];
    const float* Wq = (const float*)d_in[1];
    const float* bq = (const float*)d_in[2];
    const float* Wk = (const float*)d_in[3];
    const float* bk = (const float*)d_in[4];
    const float* Wv = (const float*)d_in[5];
    const float* bv = (const float*)d_in[6];
    float* out = (float*)d_out;

    prep_kernel<<<144, 256>>>(Wq, Wk, Wv);

    cudaFuncSetAttribute(qkv_tc_kernel, cudaFuncAttributeMaxDynamicSharedMemorySize, QKV_DSMEM);
    qkv_tc_kernel<<<BT / 128, 512, QKV_DSMEM>>>(x, bq, bk, bv);

    probe_kernel<<<1, 32>>>();   // shifts ncu's profiled slot onto qkv

    const int smem_bytes = 128 * AS_ST * 4;
    cudaFuncSetAttribute(attn_tc_kernel, cudaFuncAttributeMaxDynamicSharedMemorySize, smem_bytes);
    dim3 attn_grid(2, BB);
    attn_tc_kernel<<<attn_grid, 256, smem_bytes>>>(out);
}

// round 12
// speedup vs baseline: 5.8488x; 1.2195x over previous
#include <cuda_runtime.h>
#include <cuda_fp16.h>

#define BB 256
#define TT 256
#define CC 384
#define HS 64
#define BT (BB*TT)

typedef unsigned int u32;

// fp16 intermediates, packed half2 per u32: [row][32] u32 == [row][64] half
__device__ u32 g_qh[BT*32];
__device__ u32 g_kh[BT*32];
__device__ u32 g_vh[BT*32];
// fp16 image of W = [384 k][192 n] as half2-packed u32: [384][96]
__device__ u32 g_wimg[384*96];

// ---------------------------------------------------------------------------
// helpers
// ---------------------------------------------------------------------------
__device__ __forceinline__ u32 packh2(float a, float b) {
    __half2 h = __floats2half2_rn(a, b);
    return *(u32*)&h;
}

__device__ __forceinline__ void mma_f16(float c[4], u32 a0, u32 a1, u32 a2, u32 a3,
                                        u32 b0, u32 b1) {
    asm volatile(
        "mma.sync.aligned.m16n8k16.row.col.f32.f16.f16.f32 "
        "{%0,%1,%2,%3}, {%4,%5,%6,%7}, {%8,%9}, {%0,%1,%2,%3};\n"
        : "+f"(c[0]), "+f"(c[1]), "+f"(c[2]), "+f"(c[3])
        : "r"(a0), "r"(a1), "r"(a2), "r"(a3), "r"(b0), "r"(b1));
}
__device__ __forceinline__ void ldm_x4(u32& r0, u32& r1, u32& r2, u32& r3, u32 saddr) {
    asm volatile("ldmatrix.sync.aligned.m8n8.x4.shared.b16 {%0,%1,%2,%3}, [%4];"
                 : "=r"(r0), "=r"(r1), "=r"(r2), "=r"(r3) : "r"(saddr));
}
__device__ __forceinline__ void ldm_x4_t(u32& r0, u32& r1, u32& r2, u32& r3, u32 saddr) {
    asm volatile("ldmatrix.sync.aligned.m8n8.x4.trans.shared.b16 {%0,%1,%2,%3}, [%4];"
                 : "=r"(r0), "=r"(r1), "=r"(r2), "=r"(r3) : "r"(saddr));
}
__device__ __forceinline__ void cp_async16(u32 dst, const void* src) {
    asm volatile("cp.async.cg.shared.global [%0], [%1], 16;" :: "r"(dst), "l"(src) : "memory");
}
#define CP_COMMIT() asm volatile("cp.async.commit_group;" ::: "memory")
#define CP_WAIT0()  asm volatile("cp.async.wait_group 0;" ::: "memory")

// ---------------------------------------------------------------------------
// prep: W (fp32, [k][64] x3) -> g_wimg fp16 half2 [384 k][96 u32] (n-major)
// ---------------------------------------------------------------------------
__global__ __launch_bounds__(256) void prep_kernel(
    const float* __restrict__ Wq, const float* __restrict__ Wk,
    const float* __restrict__ Wv)
{
    int idx = blockIdx.x * 256 + threadIdx.x;   // 0..36863
    int k = idx / 96;
    int c = idx % 96;
    int n = 2 * c;
    const float* W = (n < 64) ? Wq : (n < 128 ? Wk : Wv);
    int col = n & 63;
    float2 v = *(const float2*)(W + (size_t)k * HS + col);
    g_wimg[idx] = packh2(v.x, v.y);
}

// ---------------------------------------------------------------------------
// Fused QKV projection, fp16 m16n8k16, 2 CTAs/SM.
// CTA tile 64x192, K-tile 32, grid 1024, 256 threads (8 warps: 2m x 4n,
// warp tile 32x48). W tiles cp.async double-buffered from fp16 image;
// x tiles LDG+convert double-buffered. One sync per k-tile.
// ---------------------------------------------------------------------------
#define XS_ST 20
#define WS_ST 100

__global__ __launch_bounds__(256, 2) void qkv_tc_kernel(
    const float* __restrict__ x,
    const float* __restrict__ bq, const float* __restrict__ bk,
    const float* __restrict__ bv)
{
    __shared__ u32 Wsm[2][32 * WS_ST];   // 2 x 12.8 KB
    __shared__ u32 Xs[2][64 * XS_ST];    // 2 x  5.1 KB

    const int tid  = threadIdx.x;
    const int wid  = tid >> 5;
    const int lane = tid & 31;
    const int tig  = lane & 3;
    const int gid  = lane >> 2;
    const int l7   = lane & 7;
    const int t8   = lane >> 3;
    const int wm   = wid >> 2;          // 0..1 (row group * 32)
    const int wn   = wid & 3;           // 0..3 (col group * 48)
    const int rowbase = blockIdx.x * 64;

    const u32 ws_base[2] = { (u32)__cvta_generic_to_shared(&Wsm[0][0]),
                             (u32)__cvta_generic_to_shared(&Wsm[1][0]) };
    const u32 xs_base[2] = { (u32)__cvta_generic_to_shared(&Xs[0][0]),
                             (u32)__cvta_generic_to_shared(&Xs[1][0]) };

    float acc[2][6][4];
    #pragma unroll
    for (int i = 0; i < 2; i++)
        #pragma unroll
        for (int j = 0; j < 6; j++)
            #pragma unroll
            for (int r = 0; r < 4; r++) acc[i][j][r] = 0.f;

    u32 xr[2][2];

    auto issue_w = [&](int it, int buf) {   // 768 uint4, 3/thread
        #pragma unroll
        for (int p = 0; p < 3; p++) {
            int e   = tid + 256 * p;
            int row = e / 24;
            int j   = e % 24;
            cp_async16(ws_base[buf] + 4u * (row * WS_ST + j * 4),
                       &g_wimg[(it * 32 + row) * 96 + j * 4]);
        }
    };
    auto ldg_x = [&](int k0) {   // 64x32 fp32 -> regs, 2 float4/thread
        #pragma unroll
        for (int i = 0; i < 2; i++) {
            int e = tid + 256 * i;   // 0..511
            float4 v = *(const float4*)(x + (size_t)(rowbase + (e >> 3)) * CC + k0 + ((e & 7) << 2));
            xr[i][0] = packh2(v.x, v.y); xr[i][1] = packh2(v.z, v.w);
        }
    };
    auto sts_x = [&](int buf) {
        #pragma unroll
        for (int i = 0; i < 2; i++) {
            int e = tid + 256 * i;
            *(uint2*)&Xs[buf][(e >> 3) * XS_ST + ((e & 7) << 1)] = make_uint2(xr[i][0], xr[i][1]);
        }
    };

    // prologue
    issue_w(0, 0); CP_COMMIT();
    ldg_x(0);
    CP_WAIT0();
    sts_x(0);
    __syncthreads();

    const int NIT = CC / 32;   // 12
    for (int it = 0; it < NIT; it++) {
        const int cur = it & 1;
        if (it + 1 < NIT) {
            issue_w(it + 1, cur ^ 1); CP_COMMIT();
            ldg_x((it + 1) * 32);
        }

        #pragma unroll
        for (int ks = 0; ks < 2; ks++) {
            u32 a[2][4];
            #pragma unroll
            for (int mt = 0; mt < 2; mt++) {
                u32 addr = xs_base[cur] + 4u * ((wm * 32 + mt * 16 + (t8 & 1) * 8 + l7) * XS_ST
                                                + ks * 8 + (t8 >> 1) * 4);
                ldm_x4(a[mt][0], a[mt][1], a[mt][2], a[mt][3], addr);
            }
            #pragma unroll
            for (int ntp = 0; ntp < 3; ntp++) {
                u32 b0, b1, b2, b3;
                u32 addr = ws_base[cur] + 4u * ((ks * 16 + (t8 & 1) * 8 + l7) * WS_ST
                                                + wn * 24 + (2 * ntp + (t8 >> 1)) * 4);
                ldm_x4_t(b0, b1, b2, b3, addr);
                mma_f16(acc[0][2*ntp],   a[0][0], a[0][1], a[0][2], a[0][3], b0, b1);
                mma_f16(acc[1][2*ntp],   a[1][0], a[1][1], a[1][2], a[1][3], b0, b1);
                mma_f16(acc[0][2*ntp+1], a[0][0], a[0][1], a[0][2], a[0][3], b2, b3);
                mma_f16(acc[1][2*ntp+1], a[1][0], a[1][1], a[1][2], a[1][3], b2, b3);
            }
        }

        if (it + 1 < NIT) {
            sts_x(cur ^ 1);
            CP_WAIT0();
        }
        __syncthreads();
    }

    // epilogue: bias (+Q scale), pack to half2, scatter
    #pragma unroll
    for (int nt = 0; nt < 6; nt++) {
        int col = wn * 48 + nt * 8 + 2 * tig;        // half index 0..191
        int hcol = (wn * 48 + nt * 8) / 2 + tig;     // u32 index 0..95
        u32* outp; int hc; const float* bias; float sc;
        if (col < 64)       { outp = g_qh; hc = hcol;      bias = bq; sc = 0.125f; }
        else if (col < 128) { outp = g_kh; hc = hcol - 32; bias = bk; sc = 1.f; }
        else                { outp = g_vh; hc = hcol - 64; bias = bv; sc = 1.f; }
        int c = col & 63;
        float b0 = bias[c], b1 = bias[c + 1];
        #pragma unroll
        for (int mt = 0; mt < 2; mt++) {
            int r0 = rowbase + wm * 32 + mt * 16 + gid;
            outp[(size_t)r0 * 32 + hc]       = packh2((acc[mt][nt][0] + b0) * sc,
                                                      (acc[mt][nt][1] + b1) * sc);
            outp[(size_t)(r0 + 8) * 32 + hc] = packh2((acc[mt][nt][2] + b0) * sc,
                                                      (acc[mt][nt][3] + b1) * sc);
        }
    }
}

// ---------------------------------------------------------------------------
// Flash attention, fp16 m16n8k16, cp.async DOUBLE-BUFFERED K/V.
// Grid: (2 query blocks of 128, 256 batches). 8 warps x 16 query rows.
// Smem: [Ks0|Vs0|Ks1|Vs1] x 9216B = 36.9KB (Q staging overlaps Ks0+Vs0).
// ---------------------------------------------------------------------------
#define AS_ST 36
#define KV_U32 (64 * AS_ST)   // 2304

__global__ __launch_bounds__(256, 2) void attn_tc_kernel(float* __restrict__ out)
{
    __shared__ u32 smA[4 * KV_U32];

    const int tid  = threadIdx.x;
    const int wid  = tid >> 5;
    const int lane = tid & 31;
    const int gid  = lane >> 2;
    const int tig  = lane & 3;
    const int l7   = lane & 7;
    const int t8   = lane >> 3;
    const int b  = blockIdx.y;
    const int qb = blockIdx.x;

    const u32 sm_base = (u32)__cvta_generic_to_shared(smA);
    const u32 ks_base[2] = { sm_base,                sm_base + 4u * 2 * KV_U32 };
    const u32 vs_base[2] = { sm_base + 4u * KV_U32,  sm_base + 4u * 3 * KV_U32 };

    // ---- stage Q into [Ks0|Vs0] region, extract fragments ----
    const uint4* qg = (const uint4*)(g_qh + (size_t)(b * TT + qb * 128) * 32);
    #pragma unroll
    for (int i = 0; i < 4; i++) {
        int e = tid + 256 * i;
        *(uint4*)&smA[(e >> 3) * AS_ST + (e & 7) * 4] = qg[e];
    }
    __syncthreads();

    u32 qf[4][4];
    #pragma unroll
    for (int kt = 0; kt < 4; kt++) {
        u32 addr = sm_base + 4u * ((wid * 16 + (t8 & 1) * 8 + l7) * AS_ST
                                   + kt * 8 + (t8 >> 1) * 4);
        ldm_x4(qf[kt][0], qf[kt][1], qf[kt][2], qf[kt][3], addr);
    }
    __syncthreads();   // Q region free; safe to stream K/V into buf0

    auto issue_kv = [&](int kb, int buf) {   // 1024 cp.async x 16B, 4/thread
        const u32* kg = g_kh + (size_t)(b * TT + kb * 64) * 32;
        const u32* vg = g_vh + (size_t)(b * TT + kb * 64) * 32;
        #pragma unroll
        for (int i = 0; i < 2; i++) {
            int e = tid + 256 * i;   // 0..511 uint4
            u32 off = 4u * ((e >> 3) * AS_ST + (e & 7) * 4);
            cp_async16(ks_base[buf] + off, kg + e * 4);
            cp_async16(vs_base[buf] + off, vg + e * 4);
        }
    };

    float o[8][4];
    #pragma unroll
    for (int j = 0; j < 8; j++)
        #pragma unroll
        for (int r = 0; r < 4; r++) o[j][r] = 0.f;

    float m0 = -1e30f, m1 = -1e30f, l0 = 0.f, l1 = 0.f;
    const int row0 = qb * 128 + wid * 16 + gid;
    const int row1 = row0 + 8;
    const int wrow_max = qb * 128 + wid * 16 + 15;

    const int nkb = 2 * qb + 2;
    issue_kv(0, 0); CP_COMMIT();

    for (int kb = 0; kb < nkb; kb++) {
        const int buf = kb & 1;
        const int kbase = kb * 64;
        CP_WAIT0();
        __syncthreads();
        if (kb + 1 < nkb) { issue_kv(kb + 1, buf ^ 1); CP_COMMIT(); }

        if (kbase <= wrow_max) {
            // ---- S = Q K^T ----
            float s[8][4];
            #pragma unroll
            for (int j = 0; j < 8; j++) {
                s[j][0] = s[j][1] = s[j][2] = s[j][3] = 0.f;
                u32 r0, r1, r2, r3;
                u32 arow = ks_base[buf] + 4u * ((j * 8 + l7) * AS_ST + t8 * 4);
                ldm_x4(r0, r1, r2, r3, arow);
                mma_f16(s[j], qf[0][0], qf[0][1], qf[0][2], qf[0][3], r0, r1);
                mma_f16(s[j], qf[1][0], qf[1][1], qf[1][2], qf[1][3], r2, r3);
                ldm_x4(r0, r1, r2, r3, arow + 64u);
                mma_f16(s[j], qf[2][0], qf[2][1], qf[2][2], qf[2][3], r0, r1);
                mma_f16(s[j], qf[3][0], qf[3][1], qf[3][2], qf[3][3], r2, r3);
            }
            // ---- causal mask ----
            if (kbase + 63 > row0) {
                #pragma unroll
                for (int j = 0; j < 8; j++) {
                    int key0 = kbase + j * 8 + 2 * tig;
                    int key1 = key0 + 1;
                    if (key0 > row0) s[j][0] = -1e30f;
                    if (key1 > row0) s[j][1] = -1e30f;
                    if (key0 > row1) s[j][2] = -1e30f;
                    if (key1 > row1) s[j][3] = -1e30f;
                }
            }
            // ---- online softmax ----
            float mx0 = -1e30f, mx1 = -1e30f;
            #pragma unroll
            for (int j = 0; j < 8; j++) {
                mx0 = fmaxf(mx0, fmaxf(s[j][0], s[j][1]));
                mx1 = fmaxf(mx1, fmaxf(s[j][2], s[j][3]));
            }
            mx0 = fmaxf(mx0, __shfl_xor_sync(0xffffffffu, mx0, 1));
            mx0 = fmaxf(mx0, __shfl_xor_sync(0xffffffffu, mx0, 2));
            mx1 = fmaxf(mx1, __shfl_xor_sync(0xffffffffu, mx1, 1));
            mx1 = fmaxf(mx1, __shfl_xor_sync(0xffffffffu, mx1, 2));

            float nm0 = fmaxf(m0, mx0), nm1 = fmaxf(m1, mx1);
            float cr0 = __expf(m0 - nm0), cr1 = __expf(m1 - nm1);
            m0 = nm0; m1 = nm1;

            u32 pa[8][2];
            float sum0 = 0.f, sum1 = 0.f;
            #pragma unroll
            for (int j = 0; j < 8; j++) {
                float p0 = __expf(s[j][0] - nm0);
                float p1 = __expf(s[j][1] - nm0);
                float p2 = __expf(s[j][2] - nm1);
                float p3 = __expf(s[j][3] - nm1);
                sum0 += p0 + p1; sum1 += p2 + p3;
                pa[j][0] = packh2(p0, p1);
                pa[j][1] = packh2(p2, p3);
            }
            sum0 += __shfl_xor_sync(0xffffffffu, sum0, 1);
            sum0 += __shfl_xor_sync(0xffffffffu, sum0, 2);
            sum1 += __shfl_xor_sync(0xffffffffu, sum1, 1);
            sum1 += __shfl_xor_sync(0xffffffffu, sum1, 2);
            l0 = l0 * cr0 + sum0;
            l1 = l1 * cr1 + sum1;

            #pragma unroll
            for (int j = 0; j < 8; j++) {
                o[j][0] *= cr0; o[j][1] *= cr0;
                o[j][2] *= cr1; o[j][3] *= cr1;
            }

            // ---- O += P V ----
            #pragma unroll
            for (int j = 0; j < 8; j++) {
                u32 r0, r1, r2, r3;
                u32 arow = vs_base[buf] + 4u * ((t8 * 8 + l7) * AS_ST + j * 4);
                ldm_x4_t(r0, r1, r2, r3, arow);
                mma_f16(o[j], pa[0][0], pa[0][1], pa[1][0], pa[1][1], r0, r1);
                mma_f16(o[j], pa[2][0], pa[2][1], pa[3][0], pa[3][1], r2, r3);
                ldm_x4_t(r0, r1, r2, r3, arow + 4u * 32 * AS_ST);
                mma_f16(o[j], pa[4][0], pa[4][1], pa[5][0], pa[5][1], r0, r1);
                mma_f16(o[j], pa[6][0], pa[6][1], pa[7][0], pa[7][1], r2, r3);
            }
        }
    }

    // ---- epilogue ----
    float inv0 = 1.f / l0, inv1 = 1.f / l1;
    #pragma unroll
    for (int j = 0; j < 8; j++) {
        int col = j * 8 + 2 * tig;
        *(float2*)(out + ((size_t)b * TT + row0) * HS + col) =
            make_float2(o[j][0] * inv0, o[j][1] * inv0);
        *(float2*)(out + ((size_t)b * TT + row1) * HS + col) =
            make_float2(o[j][2] * inv1, o[j][3] * inv1);
    }
}

extern "C" void kernel_launch(void* const* d_in, const int* in_sizes, int n_in,
                              void* d_out, int out_size)
{
    const float* x  = (const float*)d_in[0];
    const float* Wq = (const float*)d_in[1];
    const float* bq = (const float*)d_in[2];
    const float* Wk = (const float*)d_in[3];
    const float* bk = (const float*)d_in[4];
    const float* Wv = (const float*)d_in[5];
    const float* bv = (const float*)d_in[6];
    float* out = (float*)d_out;

    prep_kernel<<<144, 256>>>(Wq, Wk, Wv);
    qkv_tc_kernel<<<BT / 64, 256>>>(x, bq, bk, bv);

    dim3 attn_grid(2, BB);
    attn_tc_kernel<<<attn_grid, 256>>>(out);
}

// round 13
// speedup vs baseline: 6.5698x; 1.1233x over previous
#include <cuda_runtime.h>
#include <cuda_fp16.h>

#define BB 256
#define TT 256
#define CC 384
#define HS 64
#define BT (BB*TT)

typedef unsigned int u32;

// fp16 intermediates, packed half2 per u32: [row][32] u32 == [row][64] half
__device__ u32 g_qh[BT*32];
__device__ u32 g_kh[BT*32];
__device__ u32 g_vh[BT*32];
// fp16 image of W = [384 k][192 n] as half2-packed u32: [384][96]
__device__ u32 g_wimg[384*96];

// ---------------------------------------------------------------------------
// helpers
// ---------------------------------------------------------------------------
__device__ __forceinline__ u32 packh2(float a, float b) {
    __half2 h = __floats2half2_rn(a, b);
    return *(u32*)&h;
}

__device__ __forceinline__ void mma_f16(float c[4], u32 a0, u32 a1, u32 a2, u32 a3,
                                        u32 b0, u32 b1) {
    asm volatile(
        "mma.sync.aligned.m16n8k16.row.col.f32.f16.f16.f32 "
        "{%0,%1,%2,%3}, {%4,%5,%6,%7}, {%8,%9}, {%0,%1,%2,%3};\n"
        : "+f"(c[0]), "+f"(c[1]), "+f"(c[2]), "+f"(c[3])
        : "r"(a0), "r"(a1), "r"(a2), "r"(a3), "r"(b0), "r"(b1));
}
__device__ __forceinline__ void ldm_x4(u32& r0, u32& r1, u32& r2, u32& r3, u32 saddr) {
    asm volatile("ldmatrix.sync.aligned.m8n8.x4.shared.b16 {%0,%1,%2,%3}, [%4];"
                 : "=r"(r0), "=r"(r1), "=r"(r2), "=r"(r3) : "r"(saddr));
}
__device__ __forceinline__ void ldm_x4_t(u32& r0, u32& r1, u32& r2, u32& r3, u32 saddr) {
    asm volatile("ldmatrix.sync.aligned.m8n8.x4.trans.shared.b16 {%0,%1,%2,%3}, [%4];"
                 : "=r"(r0), "=r"(r1), "=r"(r2), "=r"(r3) : "r"(saddr));
}
__device__ __forceinline__ void cp_async16(u32 dst, const void* src) {
    asm volatile("cp.async.cg.shared.global [%0], [%1], 16;" :: "r"(dst), "l"(src) : "memory");
}
#define CP_COMMIT() asm volatile("cp.async.commit_group;" ::: "memory")
#define CP_WAIT0()  asm volatile("cp.async.wait_group 0;" ::: "memory")

// ---------------------------------------------------------------------------
// prep: W (fp32) -> g_wimg fp16 half2 [384 k][96 u32]; 1 uint4 store/thread
// ---------------------------------------------------------------------------
__global__ __launch_bounds__(256) void prep_kernel(
    const float* __restrict__ Wq, const float* __restrict__ Wk,
    const float* __restrict__ Wv)
{
    int idx = blockIdx.x * 256 + threadIdx.x;   // 0..9215 (uint4 index)
    int k  = idx / 24;
    int c  = (idx % 24) * 4;     // u32 col (multiple of 4)
    int n0 = 2 * c;              // n start (multiple of 8; never crosses 64-bnd)
    const float* W = (n0 < 64) ? Wq : (n0 < 128 ? Wk : Wv);
    int col = n0 & 63;
    float4 v1 = *(const float4*)(W + (size_t)k * HS + col);
    float4 v2 = *(const float4*)(W + (size_t)k * HS + col + 4);
    uint4 o;
    o.x = packh2(v1.x, v1.y); o.y = packh2(v1.z, v1.w);
    o.z = packh2(v2.x, v2.y); o.w = packh2(v2.z, v2.w);
    ((uint4*)g_wimg)[idx] = o;
}

// ---------------------------------------------------------------------------
// Fused QKV projection, fp16 m16n8k16, 2 CTAs/SM, K-TILE 64 (6 stages).
// CTA tile 64x192, grid 1024, 256 threads (8 warps: 2m x 4n, warp 32x48).
// W tiles cp.async double-buffered; x tiles LDG+convert double-buffered.
// ---------------------------------------------------------------------------
#define XS_ST 36    // 32 data u32 (64 halves) + 4 pad; 36 % 32 == 4
#define WS_ST 100   // 96 data u32 (192 halves) + 4 pad; 100 % 32 == 4

__global__ __launch_bounds__(256, 2) void qkv_tc_kernel(
    const float* __restrict__ x,
    const float* __restrict__ bq, const float* __restrict__ bk,
    const float* __restrict__ bv)
{
    __shared__ u32 Wsm[2][64 * WS_ST];   // 2 x 25.6 KB
    __shared__ u32 Xs[2][64 * XS_ST];    // 2 x  9.2 KB

    const int tid  = threadIdx.x;
    const int wid  = tid >> 5;
    const int lane = tid & 31;
    const int tig  = lane & 3;
    const int gid  = lane >> 2;
    const int l7   = lane & 7;
    const int t8   = lane >> 3;
    const int wm   = wid >> 2;          // 0..1 (row group * 32)
    const int wn   = wid & 3;           // 0..3 (col group * 48)
    const int rowbase = blockIdx.x * 64;

    const u32 ws_base[2] = { (u32)__cvta_generic_to_shared(&Wsm[0][0]),
                             (u32)__cvta_generic_to_shared(&Wsm[1][0]) };
    const u32 xs_base[2] = { (u32)__cvta_generic_to_shared(&Xs[0][0]),
                             (u32)__cvta_generic_to_shared(&Xs[1][0]) };

    float acc[2][6][4];
    #pragma unroll
    for (int i = 0; i < 2; i++)
        #pragma unroll
        for (int j = 0; j < 6; j++)
            #pragma unroll
            for (int r = 0; r < 4; r++) acc[i][j][r] = 0.f;

    u32 xr[4][2];

    auto issue_w = [&](int it, int buf) {   // 64x96 u32 = 1536 uint4, 6/thread
        #pragma unroll
        for (int p = 0; p < 6; p++) {
            int e   = tid + 256 * p;
            int row = e / 24;
            int j   = e % 24;
            cp_async16(ws_base[buf] + 4u * (row * WS_ST + j * 4),
                       &g_wimg[(it * 64 + row) * 96 + j * 4]);
        }
    };
    auto ldg_x = [&](int k0) {   // 64x64 fp32 -> regs, 4 float4/thread
        #pragma unroll
        for (int i = 0; i < 4; i++) {
            int e = tid + 256 * i;   // 0..1023
            float4 v = *(const float4*)(x + (size_t)(rowbase + (e >> 4)) * CC + k0 + ((e & 15) << 2));
            xr[i][0] = packh2(v.x, v.y); xr[i][1] = packh2(v.z, v.w);
        }
    };
    auto sts_x = [&](int buf) {
        #pragma unroll
        for (int i = 0; i < 4; i++) {
            int e = tid + 256 * i;
            *(uint2*)&Xs[buf][(e >> 4) * XS_ST + ((e & 15) << 1)] = make_uint2(xr[i][0], xr[i][1]);
        }
    };

    // prologue
    issue_w(0, 0); CP_COMMIT();
    ldg_x(0);
    CP_WAIT0();
    sts_x(0);
    __syncthreads();

    const int NIT = CC / 64;   // 6
    for (int it = 0; it < NIT; it++) {
        const int cur = it & 1;
        if (it + 1 < NIT) {
            issue_w(it + 1, cur ^ 1); CP_COMMIT();
            ldg_x((it + 1) * 64);
        }

        #pragma unroll
        for (int ks = 0; ks < 4; ks++) {
            u32 a[2][4];
            #pragma unroll
            for (int mt = 0; mt < 2; mt++) {
                u32 addr = xs_base[cur] + 4u * ((wm * 32 + mt * 16 + (t8 & 1) * 8 + l7) * XS_ST
                                                + ks * 8 + (t8 >> 1) * 4);
                ldm_x4(a[mt][0], a[mt][1], a[mt][2], a[mt][3], addr);
            }
            #pragma unroll
            for (int ntp = 0; ntp < 3; ntp++) {
                u32 b0, b1, b2, b3;
                u32 addr = ws_base[cur] + 4u * ((ks * 16 + (t8 & 1) * 8 + l7) * WS_ST
                                                + wn * 24 + (2 * ntp + (t8 >> 1)) * 4);
                ldm_x4_t(b0, b1, b2, b3, addr);
                mma_f16(acc[0][2*ntp],   a[0][0], a[0][1], a[0][2], a[0][3], b0, b1);
                mma_f16(acc[1][2*ntp],   a[1][0], a[1][1], a[1][2], a[1][3], b0, b1);
                mma_f16(acc[0][2*ntp+1], a[0][0], a[0][1], a[0][2], a[0][3], b2, b3);
                mma_f16(acc[1][2*ntp+1], a[1][0], a[1][1], a[1][2], a[1][3], b2, b3);
            }
        }

        if (it + 1 < NIT) {
            sts_x(cur ^ 1);
            CP_WAIT0();
        }
        __syncthreads();
    }

    // epilogue: bias (+Q scale), pack to half2, scatter
    #pragma unroll
    for (int nt = 0; nt < 6; nt++) {
        int col = wn * 48 + nt * 8 + 2 * tig;        // half index 0..191
        int hcol = (wn * 48 + nt * 8) / 2 + tig;     // u32 index 0..95
        u32* outp; int hc; const float* bias; float sc;
        if (col < 64)       { outp = g_qh; hc = hcol;      bias = bq; sc = 0.125f; }
        else if (col < 128) { outp = g_kh; hc = hcol - 32; bias = bk; sc = 1.f; }
        else                { outp = g_vh; hc = hcol - 64; bias = bv; sc = 1.f; }
        int c = col & 63;
        float b0 = bias[c], b1 = bias[c + 1];
        #pragma unroll
        for (int mt = 0; mt < 2; mt++) {
            int r0 = rowbase + wm * 32 + mt * 16 + gid;
            outp[(size_t)r0 * 32 + hc]       = packh2((acc[mt][nt][0] + b0) * sc,
                                                      (acc[mt][nt][1] + b1) * sc);
            outp[(size_t)(r0 + 8) * 32 + hc] = packh2((acc[mt][nt][2] + b0) * sc,
                                                      (acc[mt][nt][3] + b1) * sc);
        }
    }
}

// ---------------------------------------------------------------------------
// Flash attention, fp16 m16n8k16, cp.async double-buffered K/V.
// (unchanged from R12)
// ---------------------------------------------------------------------------
#define AS_ST 36
#define KV_U32 (64 * AS_ST)   // 2304

__global__ __launch_bounds__(256, 2) void attn_tc_kernel(float* __restrict__ out)
{
    __shared__ u32 smA[4 * KV_U32];

    const int tid  = threadIdx.x;
    const int wid  = tid >> 5;
    const int lane = tid & 31;
    const int gid  = lane >> 2;
    const int tig  = lane & 3;
    const int l7   = lane & 7;
    const int t8   = lane >> 3;
    const int b  = blockIdx.y;
    const int qb = blockIdx.x;

    const u32 sm_base = (u32)__cvta_generic_to_shared(smA);
    const u32 ks_base[2] = { sm_base,                sm_base + 4u * 2 * KV_U32 };
    const u32 vs_base[2] = { sm_base + 4u * KV_U32,  sm_base + 4u * 3 * KV_U32 };

    const uint4* qg = (const uint4*)(g_qh + (size_t)(b * TT + qb * 128) * 32);
    #pragma unroll
    for (int i = 0; i < 4; i++) {
        int e = tid + 256 * i;
        *(uint4*)&smA[(e >> 3) * AS_ST + (e & 7) * 4] = qg[e];
    }
    __syncthreads();

    u32 qf[4][4];
    #pragma unroll
    for (int kt = 0; kt < 4; kt++) {
        u32 addr = sm_base + 4u * ((wid * 16 + (t8 & 1) * 8 + l7) * AS_ST
                                   + kt * 8 + (t8 >> 1) * 4);
        ldm_x4(qf[kt][0], qf[kt][1], qf[kt][2], qf[kt][3], addr);
    }
    __syncthreads();

    auto issue_kv = [&](int kb, int buf) {
        const u32* kg = g_kh + (size_t)(b * TT + kb * 64) * 32;
        const u32* vg = g_vh + (size_t)(b * TT + kb * 64) * 32;
        #pragma unroll
        for (int i = 0; i < 2; i++) {
            int e = tid + 256 * i;
            u32 off = 4u * ((e >> 3) * AS_ST + (e & 7) * 4);
            cp_async16(ks_base[buf] + off, kg + e * 4);
            cp_async16(vs_base[buf] + off, vg + e * 4);
        }
    };

    float o[8][4];
    #pragma unroll
    for (int j = 0; j < 8; j++)
        #pragma unroll
        for (int r = 0; r < 4; r++) o[j][r] = 0.f;

    float m0 = -1e30f, m1 = -1e30f, l0 = 0.f, l1 = 0.f;
    const int row0 = qb * 128 + wid * 16 + gid;
    const int row1 = row0 + 8;
    const int wrow_max = qb * 128 + wid * 16 + 15;

    const int nkb = 2 * qb + 2;
    issue_kv(0, 0); CP_COMMIT();

    for (int kb = 0; kb < nkb; kb++) {
        const int buf = kb & 1;
        const int kbase = kb * 64;
        CP_WAIT0();
        __syncthreads();
        if (kb + 1 < nkb) { issue_kv(kb + 1, buf ^ 1); CP_COMMIT(); }

        if (kbase <= wrow_max) {
            float s[8][4];
            #pragma unroll
            for (int j = 0; j < 8; j++) {
                s[j][0] = s[j][1] = s[j][2] = s[j][3] = 0.f;
                u32 r0, r1, r2, r3;
                u32 arow = ks_base[buf] + 4u * ((j * 8 + l7) * AS_ST + t8 * 4);
                ldm_x4(r0, r1, r2, r3, arow);
                mma_f16(s[j], qf[0][0], qf[0][1], qf[0][2], qf[0][3], r0, r1);
                mma_f16(s[j], qf[1][0], qf[1][1], qf[1][2], qf[1][3], r2, r3);
                ldm_x4(r0, r1, r2, r3, arow + 64u);
                mma_f16(s[j], qf[2][0], qf[2][1], qf[2][2], qf[2][3], r0, r1);
                mma_f16(s[j], qf[3][0], qf[3][1], qf[3][2], qf[3][3], r2, r3);
            }
            if (kbase + 63 > row0) {
                #pragma unroll
                for (int j = 0; j < 8; j++) {
                    int key0 = kbase + j * 8 + 2 * tig;
                    int key1 = key0 + 1;
                    if (key0 > row0) s[j][0] = -1e30f;
                    if (key1 > row0) s[j][1] = -1e30f;
                    if (key0 > row1) s[j][2] = -1e30f;
                    if (key1 > row1) s[j][3] = -1e30f;
                }
            }
            float mx0 = -1e30f, mx1 = -1e30f;
            #pragma unroll
            for (int j = 0; j < 8; j++) {
                mx0 = fmaxf(mx0, fmaxf(s[j][0], s[j][1]));
                mx1 = fmaxf(mx1, fmaxf(s[j][2], s[j][3]));
            }
            mx0 = fmaxf(mx0, __shfl_xor_sync(0xffffffffu, mx0, 1));
            mx0 = fmaxf(mx0, __shfl_xor_sync(0xffffffffu, mx0, 2));
            mx1 = fmaxf(mx1, __shfl_xor_sync(0xffffffffu, mx1, 1));
            mx1 = fmaxf(mx1, __shfl_xor_sync(0xffffffffu, mx1, 2));

            float nm0 = fmaxf(m0, mx0), nm1 = fmaxf(m1, mx1);
            float cr0 = __expf(m0 - nm0), cr1 = __expf(m1 - nm1);
            m0 = nm0; m1 = nm1;

            u32 pa[8][2];
            float sum0 = 0.f, sum1 = 0.f;
            #pragma unroll
            for (int j = 0; j < 8; j++) {
                float p0 = __expf(s[j][0] - nm0);
                float p1 = __expf(s[j][1] - nm0);
                float p2 = __expf(s[j][2] - nm1);
                float p3 = __expf(s[j][3] - nm1);
                sum0 += p0 + p1; sum1 += p2 + p3;
                pa[j][0] = packh2(p0, p1);
                pa[j][1] = packh2(p2, p3);
            }
            sum0 += __shfl_xor_sync(0xffffffffu, sum0, 1);
            sum0 += __shfl_xor_sync(0xffffffffu, sum0, 2);
            sum1 += __shfl_xor_sync(0xffffffffu, sum1, 1);
            sum1 += __shfl_xor_sync(0xffffffffu, sum1, 2);
            l0 = l0 * cr0 + sum0;
            l1 = l1 * cr1 + sum1;

            #pragma unroll
            for (int j = 0; j < 8; j++) {
                o[j][0] *= cr0; o[j][1] *= cr0;
                o[j][2] *= cr1; o[j][3] *= cr1;
            }

            #pragma unroll
            for (int j = 0; j < 8; j++) {
                u32 r0, r1, r2, r3;
                u32 arow = vs_base[buf] + 4u * ((t8 * 8 + l7) * AS_ST + j * 4);
                ldm_x4_t(r0, r1, r2, r3, arow);
                mma_f16(o[j], pa[0][0], pa[0][1], pa[1][0], pa[1][1], r0, r1);
                mma_f16(o[j], pa[2][0], pa[2][1], pa[3][0], pa[3][1], r2, r3);
                ldm_x4_t(r0, r1, r2, r3, arow + 4u * 32 * AS_ST);
                mma_f16(o[j], pa[4][0], pa[4][1], pa[5][0], pa[5][1], r0, r1);
                mma_f16(o[j], pa[6][0], pa[6][1], pa[7][0], pa[7][1], r2, r3);
            }
        }
    }

    float inv0 = 1.f / l0, inv1 = 1.f / l1;
    #pragma unroll
    for (int j = 0; j < 8; j++) {
        int col = j * 8 + 2 * tig;
        *(float2*)(out + ((size_t)b * TT + row0) * HS + col) =
            make_float2(o[j][0] * inv0, o[j][1] * inv0);
        *(float2*)(out + ((size_t)b * TT + row1) * HS + col) =
            make_float2(o[j][2] * inv1, o[j][3] * inv1);
    }
}

extern "C" void kernel_launch(void* const* d_in, const int* in_sizes, int n_in,
                              void* d_out, int out_size)
{
    const float* x  = (const float*)d_in[0];
    const float* Wq = (const float*)d_in[1];
    const float* bq = (const float*)d_in[2];
    const float* Wk = (const float*)d_in[3];
    const float* bk = (const float*)d_in[4];
    const float* Wv = (const float*)d_in[5];
    const float* bv = (const float*)d_in[6];
    float* out = (float*)d_out;

    prep_kernel<<<36, 256>>>(Wq, Wk, Wv);
    qkv_tc_kernel<<<BT / 64, 256>>>(x, bq, bk, bv);

    dim3 attn_grid(2, BB);
    attn_tc_kernel<<<attn_grid, 256>>>(out);
}